// round 10
// baseline (speedup 1.0000x reference)
#include <cuda_runtime.h>
#include <cuda_bf16.h>
#include <cstddef>
#include <cstdint>

// Problem constants
#define BB    4096      // batch
#define LAT   256
#define HH    512
#define AA    64
#define LL    128
#define NSTEP 127       // L-1 sequential GRU steps
#define KCAT  576       // H + A
#define NCAT  1536      // 3H
#define MALL  (NSTEP * BB)   // 520192 rows

typedef __nv_bfloat16 bf16;

// -------------------- scratch (__device__ globals, no allocs) --------------------
__device__ __align__(256) bf16  g_lat_h[BB * LAT],  g_lat_l[BB * LAT];
// ping-pong [h | x] buffers (read s&1, write (s+1)&1) — avoids cross-CTA WAR in fused step
__device__ __align__(256) bf16  g_hx_h [2 * BB * KCAT], g_hx_l [2 * BB * KCAT];
__device__ __align__(256) bf16  g_t1_h [BB * HH],   g_t1_l [BB * HH];
__device__ __align__(256) bf16  g_t2_h [BB * HH],   g_t2_l [BB * HH];
__device__ __align__(256) bf16  g_hall_h[(size_t)MALL * HH];
__device__ __align__(256) bf16  g_hall_l[(size_t)MALL * HH];
__device__ __align__(256) bf16  g_p1_h [(size_t)MALL * HH];
__device__ __align__(256) bf16  g_p1_l [(size_t)MALL * HH];
__device__ __align__(256) bf16  g_p2_h [(size_t)MALL * AA];
__device__ __align__(256) bf16  g_p2_l [(size_t)MALL * AA];
// precomputed n-gate input projection for all steps: inn[s*BB+b][j]
__device__ __align__(256) float g_inn  [(size_t)MALL * HH];
// all-step inputs x as split planes [MALL x 64]
__device__ __align__(256) bf16  g_x_h  [(size_t)MALL * AA], g_x_l[(size_t)MALL * AA];
// interleaved recurrent weight: row 3j+g <- [W_hh | W_ih(r,z) / 0(n)]
__device__ __align__(256) bf16  g_wc_h [NCAT * KCAT], g_wc_l [NCAT * KCAT];
__device__ __align__(256) bf16  g_win_h[HH * AA],     g_win_l[HH * AA];    // W_ih n-gate rows
__device__ __align__(256) bf16  g_wd1_h[HH * LAT],    g_wd1_l[HH * LAT];
__device__ __align__(256) bf16  g_wd2_h[HH * HH],     g_wd2_l[HH * HH];
__device__ __align__(256) bf16  g_wd3_h[HH * HH],     g_wd3_l[HH * HH];
__device__ __align__(256) bf16  g_wm1_h[HH * HH],     g_wm1_l[HH * HH];
__device__ __align__(256) bf16  g_wm2_h[AA * HH],     g_wm2_l[AA * HH];
__device__ __align__(256) bf16  g_wm3_h[AA * AA],     g_wm3_l[AA * AA];
__device__ __align__(256) float g_bcat[NCAT];          // interleaved triple bias

// -------------------- PTX helpers --------------------
__device__ __forceinline__ uint32_t smem_u32(const void* p) {
    return (uint32_t)__cvta_generic_to_shared(p);
}
__device__ __forceinline__ void cpasync16(uint32_t s, const void* g) {
    asm volatile("cp.async.cg.shared.global [%0], [%1], 16;\n" :: "r"(s), "l"(g));
}
__device__ __forceinline__ void ldmx4(uint32_t& r0, uint32_t& r1, uint32_t& r2, uint32_t& r3,
                                      uint32_t addr) {
    asm volatile("ldmatrix.sync.aligned.m8n8.x4.shared.b16 {%0,%1,%2,%3}, [%4];\n"
                 : "=r"(r0), "=r"(r1), "=r"(r2), "=r"(r3) : "r"(addr));
}
__device__ __forceinline__ void mma16816(float* c, const uint32_t* a, const uint32_t* b) {
    asm volatile(
        "mma.sync.aligned.m16n8k16.row.col.f32.bf16.bf16.f32 "
        "{%0,%1,%2,%3}, {%4,%5,%6,%7}, {%8,%9}, {%0,%1,%2,%3};\n"
        : "+f"(c[0]), "+f"(c[1]), "+f"(c[2]), "+f"(c[3])
        : "r"(a[0]), "r"(a[1]), "r"(a[2]), "r"(a[3]), "r"(b[0]), "r"(b[1]));
}
__device__ __forceinline__ void fsplit(float v, bf16& h, bf16& l) {
    h = __float2bfloat16(v);
    l = __float2bfloat16(v - __bfloat162float(h));
}
// 64B-row swizzle: chunk q = c ^ ((r>>1)&3) -> 8 consecutive rows hit 8 distinct bank groups
__device__ __forceinline__ uint32_t swz(int r, int c) {
    return (uint32_t)(r * 64 + ((c ^ ((r >> 1) & 3)) << 4));
}

// -------------------- mma.sync split-bf16 GEMM (generic) --------------------
// C[m,n] = act( sum_k A[m,k]*Bw[n,k] + bias[n] ); A,B as bf16 hi/lo planes.
// acc = Ah*Bh + Ah*Bl + Al*Bh, fp32 accum. BM=128, BK=32, BN template.
// M%128==0, K%32==0; N guarded vs col tile.
// act: 0 none, 1 tanh. omode: 0 fp32 C, 1 split bf16 planes, 2 fp32 scatter to out.
template<int BN>
__global__ void __launch_bounds__(256)
mma_gemm(const bf16* __restrict__ Ahi, const bf16* __restrict__ Alo,
         const bf16* __restrict__ Bhi, const bf16* __restrict__ Blo,
         const float* __restrict__ bias,
         float* __restrict__ Cf, bf16* __restrict__ Chi, bf16* __restrict__ Clo,
         int M, int N, int K, int ldc, int act, int omode)
{
    constexpr int WN  = BN / 2;
    constexpr int NT  = WN / 8;
    constexpr int NT2 = NT / 2;
    constexpr int A_BYTES = 128 * 64;
    constexpr int B_BYTES = BN * 64;
    constexpr int STAGE   = 2 * A_BYTES + 2 * B_BYTES;

    extern __shared__ char smem[];
    const uint32_t sbase = smem_u32(smem);
    const int tid = threadIdx.x;
    const int lane = tid & 31, wid = tid >> 5;
    const int wm = wid & 3, wn = wid >> 2;
    const int row0 = blockIdx.y * 128;
    const int col0 = blockIdx.x * BN;
    const int KT = K >> 5;

    float acc[2][NT][4];
#pragma unroll
    for (int t = 0; t < 2; t++)
#pragma unroll
        for (int n = 0; n < NT; n++)
#pragma unroll
            for (int i = 0; i < 4; i++) acc[t][n][i] = 0.f;

    auto load_stage = [&](int kt, int s) {
        const int k0 = kt << 5;
        const uint32_t so = sbase + s * STAGE;
#pragma unroll
        for (int i = 0; i < 2; i++) {
            int l = tid + i * 256;
            int r = l >> 2, c = l & 3;
            uint32_t sa = so + swz(r, c);
            size_t go = (size_t)(row0 + r) * K + k0 + c * 8;
            cpasync16(sa,           Ahi + go);
            cpasync16(sa + A_BYTES, Alo + go);
        }
#pragma unroll
        for (int i = 0; i < (BN * 4 + 255) / 256; i++) {
            int l = tid + i * 256;
            if (l < BN * 4) {
                int r = l >> 2, c = l & 3;
                uint32_t sb = so + 2 * A_BYTES + swz(r, c);
                size_t go = (size_t)(col0 + r) * K + k0 + c * 8;
                cpasync16(sb,           Bhi + go);
                cpasync16(sb + B_BYTES, Blo + go);
            }
        }
        asm volatile("cp.async.commit_group;\n" ::: "memory");
    };

    load_stage(0, 0);
    for (int kt = 0; kt < KT; kt++) {
        if (kt + 1 < KT) {
            load_stage(kt + 1, (kt + 1) & 1);
            asm volatile("cp.async.wait_group 1;\n" ::: "memory");
        } else {
            asm volatile("cp.async.wait_group 0;\n" ::: "memory");
        }
        __syncthreads();

        const uint32_t so = sbase + (kt & 1) * STAGE;
#pragma unroll
        for (int ks = 0; ks < 2; ks++) {
            uint32_t ah[2][4], al[2][4];
#pragma unroll
            for (int t = 0; t < 2; t++) {
                int r = wm * 32 + t * 16 + (lane & 7) + ((lane >> 3) & 1) * 8;
                int c = ks * 2 + (lane >> 4);
                uint32_t addr = so + swz(r, c);
                ldmx4(ah[t][0], ah[t][1], ah[t][2], ah[t][3], addr);
                ldmx4(al[t][0], al[t][1], al[t][2], al[t][3], addr + A_BYTES);
            }
#pragma unroll
            for (int p = 0; p < NT2; p++) {
                int r = wn * WN + p * 16 + (lane & 7) + (lane >> 4) * 8;
                int c = ks * 2 + ((lane >> 3) & 1);
                uint32_t addr = so + 2 * A_BYTES + swz(r, c);
                uint32_t bh[4], bl[4];
                ldmx4(bh[0], bh[1], bh[2], bh[3], addr);
                ldmx4(bl[0], bl[1], bl[2], bl[3], addr + B_BYTES);
                // term-outermost: same-acc reuse distance 4 (was 1) to break RAW chains
#pragma unroll
                for (int t = 0; t < 2; t++) {
                    mma16816(acc[t][2 * p],     ah[t], bh);
                    mma16816(acc[t][2 * p + 1], ah[t], bh + 2);
                }
#pragma unroll
                for (int t = 0; t < 2; t++) {
                    mma16816(acc[t][2 * p],     ah[t], bl);
                    mma16816(acc[t][2 * p + 1], ah[t], bl + 2);
                }
#pragma unroll
                for (int t = 0; t < 2; t++) {
                    mma16816(acc[t][2 * p],     al[t], bh);
                    mma16816(acc[t][2 * p + 1], al[t], bh + 2);
                }
            }
        }
        __syncthreads();
    }

#pragma unroll
    for (int t = 0; t < 2; t++) {
#pragma unroll
        for (int nt = 0; nt < NT; nt++) {
            int col = col0 + wn * WN + nt * 8 + (lane & 3) * 2;
            float b0 = bias[col], b1 = bias[col + 1];
#pragma unroll
            for (int h = 0; h < 2; h++) {
                int m = row0 + wm * 32 + t * 16 + (lane >> 2) + h * 8;
                float vx = acc[t][nt][2 * h + 0] + b0;
                float vy = acc[t][nt][2 * h + 1] + b1;
                if (act) { vx = tanhf(vx); vy = tanhf(vy); }
                if (omode == 0) {
                    size_t idx = (size_t)m * ldc + col;
                    Cf[idx] = vx; Cf[idx + 1] = vy;
                } else if (omode == 1) {
                    size_t idx = (size_t)m * ldc + col;
                    bf16 hx, lx; fsplit(vx, hx, lx);
                    bf16 hy, ly; fsplit(vy, hy, ly);
                    Chi[idx] = hx; Chi[idx + 1] = hy;
                    Clo[idx] = lx; Clo[idx + 1] = ly;
                } else {
                    int b = m & (BB - 1), s = m >> 12;
                    size_t idx = (size_t)b * (LL * AA) + (size_t)(s + 1) * AA + col;
                    Cf[idx] = vx; Cf[idx + 1] = vy;
                }
            }
        }
    }
}

// -------------------- fused GRU step: GEMM (interleaved triples) + gates --------------------
// A = [h|x] read buffer (planes), B = interleaved wcat' (row 3j+g). BN=96 so each
// CTA owns complete (r,z,n) triples. Epilogue stages O tile in smem, applies the
// GRU gate math using precomputed inn, writes h_new to hall + write hx buffer.
#define ST_A 8192                  // 128 rows x 64B (one A plane, BK=32)
#define ST_B 6144                  // 96 rows x 64B
#define ST_STAGE (2 * ST_A + 2 * ST_B)       // 28672
#define ST_SMEM  (2 * ST_STAGE)              // 57344 (>= O tile 128*97*4=49664)
#define ROWF 97

__global__ void __launch_bounds__(256)
step_kernel(const bf16* __restrict__ Ahi, const bf16* __restrict__ Alo,   // read hx buffer
            const bf16* __restrict__ Bhi, const bf16* __restrict__ Blo,   // wcat' planes
            const float* __restrict__ bias,                               // bcat'
            const float* __restrict__ inn_s,                              // + s*BB*HH
            const float* __restrict__ target,
            bf16* __restrict__ hxw_h, bf16* __restrict__ hxw_l,           // write hx buffer
            bf16* __restrict__ hall_h, bf16* __restrict__ hall_l,         // + s*BB*HH
            int s)
{
    constexpr int BN = 96, WN = 48, NT = 6, NT2 = 3;
    extern __shared__ char smem[];
    float* sO = (float*)smem;
    const uint32_t sbase = smem_u32(smem);
    const int tid = threadIdx.x;
    const int lane = tid & 31, wid = tid >> 5;
    const int wm = wid & 3, wn = wid >> 2;
    const int row0 = blockIdx.y * 128;
    const int col0 = blockIdx.x * BN;
    const int KT = KCAT >> 5;   // 18

    float acc[2][NT][4];
#pragma unroll
    for (int t = 0; t < 2; t++)
#pragma unroll
        for (int n = 0; n < NT; n++)
#pragma unroll
            for (int i = 0; i < 4; i++) acc[t][n][i] = 0.f;

    auto load_stage = [&](int kt, int st) {
        const int k0 = kt << 5;
        const uint32_t so = sbase + st * ST_STAGE;
#pragma unroll
        for (int i = 0; i < 2; i++) {                  // A: 512 chunk-loads
            int l = tid + i * 256;
            int r = l >> 2, c = l & 3;
            uint32_t sa = so + swz(r, c);
            size_t go = (size_t)(row0 + r) * KCAT + k0 + c * 8;
            cpasync16(sa,        Ahi + go);
            cpasync16(sa + ST_A, Alo + go);
        }
#pragma unroll
        for (int i = 0; i < 2; i++) {                  // B: 384 chunk-loads
            int l = tid + i * 256;
            if (l < 384) {
                int r = l >> 2, c = l & 3;
                uint32_t sb = so + 2 * ST_A + swz(r, c);
                size_t go = (size_t)(col0 + r) * KCAT + k0 + c * 8;
                cpasync16(sb,        Bhi + go);
                cpasync16(sb + ST_B, Blo + go);
            }
        }
        asm volatile("cp.async.commit_group;\n" ::: "memory");
    };

    load_stage(0, 0);
    for (int kt = 0; kt < KT; kt++) {
        if (kt + 1 < KT) {
            load_stage(kt + 1, (kt + 1) & 1);
            asm volatile("cp.async.wait_group 1;\n" ::: "memory");
        } else {
            asm volatile("cp.async.wait_group 0;\n" ::: "memory");
        }
        __syncthreads();

        const uint32_t so = sbase + (kt & 1) * ST_STAGE;
#pragma unroll
        for (int ks = 0; ks < 2; ks++) {
            uint32_t ah[2][4], al[2][4];
#pragma unroll
            for (int t = 0; t < 2; t++) {
                int r = wm * 32 + t * 16 + (lane & 7) + ((lane >> 3) & 1) * 8;
                int c = ks * 2 + (lane >> 4);
                uint32_t addr = so + swz(r, c);
                ldmx4(ah[t][0], ah[t][1], ah[t][2], ah[t][3], addr);
                ldmx4(al[t][0], al[t][1], al[t][2], al[t][3], addr + ST_A);
            }
#pragma unroll
            for (int p = 0; p < NT2; p++) {
                int r = wn * WN + p * 16 + (lane & 7) + (lane >> 4) * 8;
                int c = ks * 2 + ((lane >> 3) & 1);
                uint32_t addr = so + 2 * ST_A + swz(r, c);
                uint32_t bh[4], bl[4];
                ldmx4(bh[0], bh[1], bh[2], bh[3], addr);
                ldmx4(bl[0], bl[1], bl[2], bl[3], addr + ST_B);
#pragma unroll
                for (int t = 0; t < 2; t++) {
                    mma16816(acc[t][2 * p],     ah[t], bh);
                    mma16816(acc[t][2 * p + 1], ah[t], bh + 2);
                }
#pragma unroll
                for (int t = 0; t < 2; t++) {
                    mma16816(acc[t][2 * p],     ah[t], bl);
                    mma16816(acc[t][2 * p + 1], ah[t], bl + 2);
                }
#pragma unroll
                for (int t = 0; t < 2; t++) {
                    mma16816(acc[t][2 * p],     al[t], bh);
                    mma16816(acc[t][2 * p + 1], al[t], bh + 2);
                }
            }
        }
        __syncthreads();
    }

    // stage O tile (+bias) to smem
#pragma unroll
    for (int t = 0; t < 2; t++) {
#pragma unroll
        for (int nt = 0; nt < NT; nt++) {
            int col = wn * WN + nt * 8 + (lane & 3) * 2;
            float b0 = bias[col0 + col], b1 = bias[col0 + col + 1];
#pragma unroll
            for (int h = 0; h < 2; h++) {
                int r = wm * 32 + t * 16 + (lane >> 2) + h * 8;
                sO[r * ROWF + col]     = acc[t][nt][2 * h + 0] + b0;
                sO[r * ROWF + col + 1] = acc[t][nt][2 * h + 1] + b1;
            }
        }
    }
    __syncthreads();

    // gate phase: 128 rows x 32 triples per CTA, 16 items/thread
#pragma unroll
    for (int it = 0; it < 16; it++) {
        int idx = tid + it * 256;
        int r = idx & 127, j = idx >> 7;       // j in 0..31
        int b = row0 + r;
        int jg = blockIdx.x * 32 + j;          // global hidden index
        float o_r  = sO[r * ROWF + 3 * j];
        float o_z  = sO[r * ROWF + 3 * j + 1];
        float o_hn = sO[r * ROWF + 3 * j + 2];
        float innv = inn_s[(size_t)b * HH + jg];
        size_t hxi = (size_t)b * KCAT + jg;
        float hp = __bfloat162float(Ahi[hxi]) + __bfloat162float(Alo[hxi]);
        float rg = 1.f / (1.f + expf(-o_r));
        float zg = 1.f / (1.f + expf(-o_z));
        float n  = tanhf(innv + rg * o_hn);
        float hv = (1.f - zg) * n + zg * hp;
        bf16 hh, hl; fsplit(hv, hh, hl);
        hall_h[(size_t)b * HH + jg] = hh;
        hall_l[(size_t)b * HH + jg] = hl;
        hxw_h[hxi] = hh;
        hxw_l[hxi] = hl;
        // stage next x into the WRITE buffer (one writer per (b,a): jg<64)
        if (jg < AA && s < NSTEP - 1) {
            float xv = target[(size_t)b * (LL * AA) + (size_t)(s + 1) * AA + jg];
            bf16 xh, xl; fsplit(xv, xh, xl);
            hxw_h[(size_t)b * KCAT + HH + jg] = xh;
            hxw_l[(size_t)b * KCAT + HH + jg] = xl;
        }
    }
}

// -------------------- prep: interleaved wcat' + bias' + W_ihn planes --------------------
__global__ void prep_kernel(const float* __restrict__ W_hh, const float* __restrict__ W_ih,
                            const float* __restrict__ b_hh, const float* __restrict__ b_ih)
{
    int i = blockIdx.x * blockDim.x + threadIdx.x;
    if (i < NCAT * KCAT) {
        int n = i / KCAT, k = i % KCAT;
        int g = n % 3, jj = n / 3;             // interleaved row 3j+g
        int src = g * HH + jj;
        float v;
        if (k < HH)     v = W_hh[(size_t)src * HH + k];
        else if (g < 2) v = W_ih[(size_t)src * AA + (k - HH)];
        else            v = 0.f;               // n-gate x-part handled via precomputed inn
        fsplit(v, g_wc_h[i], g_wc_l[i]);
    }
    if (i < NCAT) {
        int g = i % 3, jj = i / 3;
        int src = g * HH + jj;
        g_bcat[i] = b_hh[src] + ((g < 2) ? b_ih[src] : 0.f);
    }
    if (i < HH * AA) {
        fsplit(W_ih[(size_t)(2 * HH) * AA + i], g_win_h[i], g_win_l[i]);
    }
}

// -------------------- split / xall / bos --------------------
__global__ void split_kernel(const float* __restrict__ src, bf16* __restrict__ hi,
                             bf16* __restrict__ lo, int n)
{
    int i = blockIdx.x * blockDim.x + threadIdx.x;
    if (i < n) fsplit(src[i], hi[i], lo[i]);
}

__global__ void xall_kernel(const float* __restrict__ target)
{
    int idx = blockIdx.x * blockDim.x + threadIdx.x;     // MALL*AA items
    if (idx >= MALL * AA) return;
    int m = idx >> 6, a = idx & 63;
    int s = m >> 12, b = m & (BB - 1);
    float v = (s == 0) ? ((a == 0) ? 16.f : -16.f)
                       : target[(size_t)b * (LL * AA) + (size_t)s * AA + a];
    fsplit(v, g_x_h[idx], g_x_l[idx]);
}

__global__ void bos_kernel(float* __restrict__ out)
{
    int i = blockIdx.x * blockDim.x + threadIdx.x;
    if (i >= BB * AA) return;
    int b = i >> 6, a = i & 63;
    float v = (a == 0) ? 16.f : -16.f;
    out[(size_t)b * (LL * AA) + a] = v;
    g_hx_h[(size_t)b * KCAT + HH + a] = __float2bfloat16(v);   // buffer 0 x-part (exact)
    g_hx_l[(size_t)b * KCAT + HH + a] = __float2bfloat16(0.f);
}

// -------------------- launch --------------------
extern "C" void kernel_launch(void* const* d_in, const int* in_sizes, int n_in,
                              void* d_out, int out_size)
{
    const float* latent = (const float*)d_in[0];
    const float* target = (const float*)d_in[1];
    const float* Wd1 = (const float*)d_in[2];
    const float* bd1 = (const float*)d_in[3];
    const float* Wd2 = (const float*)d_in[4];
    const float* bd2 = (const float*)d_in[5];
    const float* Wd3 = (const float*)d_in[6];
    const float* bd3 = (const float*)d_in[7];
    const float* W_ih = (const float*)d_in[8];
    const float* W_hh = (const float*)d_in[9];
    const float* b_ih = (const float*)d_in[10];
    const float* b_hh = (const float*)d_in[11];
    const float* Wm1 = (const float*)d_in[12];
    const float* bm1 = (const float*)d_in[13];
    const float* Wm2 = (const float*)d_in[14];
    const float* bm2 = (const float*)d_in[15];
    const float* Wm3 = (const float*)d_in[16];
    const float* bm3 = (const float*)d_in[17];
    float* out = (float*)d_out;

    bf16 *lath, *latl, *hxh, *hxl, *t1h, *t1l, *t2h, *t2l;
    bf16 *hallh, *halll, *p1h, *p1l, *p2h, *p2l, *xh, *xl;
    bf16 *wch, *wcl, *winh, *winl, *wd1h, *wd1l, *wd2h, *wd2l, *wd3h, *wd3l;
    bf16 *wm1h, *wm1l, *wm2h, *wm2l, *wm3h, *wm3l;
    float *inn, *bcat;
    cudaGetSymbolAddress((void**)&lath, g_lat_h);  cudaGetSymbolAddress((void**)&latl, g_lat_l);
    cudaGetSymbolAddress((void**)&hxh,  g_hx_h);   cudaGetSymbolAddress((void**)&hxl,  g_hx_l);
    cudaGetSymbolAddress((void**)&t1h,  g_t1_h);   cudaGetSymbolAddress((void**)&t1l,  g_t1_l);
    cudaGetSymbolAddress((void**)&t2h,  g_t2_h);   cudaGetSymbolAddress((void**)&t2l,  g_t2_l);
    cudaGetSymbolAddress((void**)&hallh,g_hall_h); cudaGetSymbolAddress((void**)&halll,g_hall_l);
    cudaGetSymbolAddress((void**)&p1h,  g_p1_h);   cudaGetSymbolAddress((void**)&p1l,  g_p1_l);
    cudaGetSymbolAddress((void**)&p2h,  g_p2_h);   cudaGetSymbolAddress((void**)&p2l,  g_p2_l);
    cudaGetSymbolAddress((void**)&xh,   g_x_h);    cudaGetSymbolAddress((void**)&xl,   g_x_l);
    cudaGetSymbolAddress((void**)&wch,  g_wc_h);   cudaGetSymbolAddress((void**)&wcl,  g_wc_l);
    cudaGetSymbolAddress((void**)&winh, g_win_h);  cudaGetSymbolAddress((void**)&winl, g_win_l);
    cudaGetSymbolAddress((void**)&wd1h, g_wd1_h);  cudaGetSymbolAddress((void**)&wd1l, g_wd1_l);
    cudaGetSymbolAddress((void**)&wd2h, g_wd2_h);  cudaGetSymbolAddress((void**)&wd2l, g_wd2_l);
    cudaGetSymbolAddress((void**)&wd3h, g_wd3_h);  cudaGetSymbolAddress((void**)&wd3l, g_wd3_l);
    cudaGetSymbolAddress((void**)&wm1h, g_wm1_h);  cudaGetSymbolAddress((void**)&wm1l, g_wm1_l);
    cudaGetSymbolAddress((void**)&wm2h, g_wm2_h);  cudaGetSymbolAddress((void**)&wm2l, g_wm2_l);
    cudaGetSymbolAddress((void**)&wm3h, g_wm3_h);  cudaGetSymbolAddress((void**)&wm3l, g_wm3_l);
    cudaGetSymbolAddress((void**)&inn,  g_inn);
    cudaGetSymbolAddress((void**)&bcat, g_bcat);

    const int SM128 = 2 * (2 * 128 * 64 + 2 * 128 * 64);   // 65536
    const int SM64  = 2 * (2 * 128 * 64 + 2 *  64 * 64);   // 49152
    cudaFuncSetAttribute(mma_gemm<128>, cudaFuncAttributeMaxDynamicSharedMemorySize, SM128);
    cudaFuncSetAttribute(mma_gemm<64>,  cudaFuncAttributeMaxDynamicSharedMemorySize, SM64);
    cudaFuncSetAttribute(step_kernel,   cudaFuncAttributeMaxDynamicSharedMemorySize, ST_SMEM);

    // weight prep + input staging
    prep_kernel<<<(NCAT * KCAT + 255) / 256, 256>>>(W_hh, W_ih, b_hh, b_ih);
    split_kernel<<<(HH * LAT + 255) / 256, 256>>>(Wd1, wd1h, wd1l, HH * LAT);
    split_kernel<<<(HH * HH + 255) / 256, 256>>>(Wd2, wd2h, wd2l, HH * HH);
    split_kernel<<<(HH * HH + 255) / 256, 256>>>(Wd3, wd3h, wd3l, HH * HH);
    split_kernel<<<(HH * HH + 255) / 256, 256>>>(Wm1, wm1h, wm1l, HH * HH);
    split_kernel<<<(AA * HH + 255) / 256, 256>>>(Wm2, wm2h, wm2l, AA * HH);
    split_kernel<<<(AA * AA + 255) / 256, 256>>>(Wm3, wm3h, wm3l, AA * AA);
    split_kernel<<<(BB * LAT + 255) / 256, 256>>>(latent, lath, latl, BB * LAT);
    xall_kernel<<<(MALL * AA + 255) / 256, 256>>>(target);
    bos_kernel<<<(BB * AA + 255) / 256, 256>>>(out);

    // precompute inn[s,b,j] = x_s . W_ihn + b_ihn for ALL steps (one GEMM)
    mma_gemm<128><<<dim3(HH / 128, MALL / 128), 256, SM128>>>(
        xh, xl, winh, winl, b_ih + 2 * HH, inn, nullptr, nullptr,
        MALL, HH, AA, HH, 0, 0);

    // initial hidden -> hx buffer 0
    mma_gemm<128><<<dim3(HH / 128, BB / 128), 256, SM128>>>(
        lath, latl, wd1h, wd1l, bd1, nullptr, t1h, t1l, BB, HH, LAT, HH, 1, 1);
    mma_gemm<128><<<dim3(HH / 128, BB / 128), 256, SM128>>>(
        t1h, t1l, wd2h, wd2l, bd2, nullptr, t2h, t2l, BB, HH, HH, HH, 1, 1);
    mma_gemm<128><<<dim3(HH / 128, BB / 128), 256, SM128>>>(
        t2h, t2l, wd3h, wd3l, bd3, nullptr, hxh, hxl, BB, HH, HH, KCAT, 0, 1);

    // sequential GRU core: fused GEMM+gates, ping-pong hx buffers
    for (int s = 0; s < NSTEP; s++) {
        const size_t rb = (size_t)(s & 1) * BB * KCAT;
        const size_t wb = (size_t)((s + 1) & 1) * BB * KCAT;
        step_kernel<<<dim3(NCAT / 96, BB / 128), 256, ST_SMEM>>>(
            hxh + rb, hxl + rb, wch, wcl, bcat,
            inn + (size_t)s * BB * HH, target,
            hxh + wb, hxl + wb,
            hallh + (size_t)s * BB * HH, halll + (size_t)s * BB * HH, s);
    }

    // deferred prediction head
    mma_gemm<128><<<dim3(HH / 128, MALL / 128), 256, SM128>>>(
        hallh, halll, wm1h, wm1l, bm1, nullptr, p1h, p1l, MALL, HH, HH, HH, 1, 1);
    mma_gemm<64><<<dim3(1, MALL / 128), 256, SM64>>>(
        p1h, p1l, wm2h, wm2l, bm2, nullptr, p2h, p2l, MALL, AA, HH, AA, 1, 1);
    mma_gemm<64><<<dim3(1, MALL / 128), 256, SM64>>>(
        p2h, p2l, wm3h, wm3l, bm3, out, nullptr, nullptr, MALL, AA, AA, 0, 0, 2);
}

// round 13
// speedup vs baseline: 1.8922x; 1.8922x over previous
#include <cuda_runtime.h>
#include <cuda_bf16.h>
#include <cstddef>
#include <cstdint>

// Problem constants
#define BB    4096      // batch
#define LAT   256
#define HH    512
#define AA    64
#define LL    128
#define NSTEP 127       // L-1 sequential GRU steps
#define KCAT  576       // H + A
#define NCAT  1536      // 3H
#define MALL  (NSTEP * BB)   // 520192 rows

typedef __nv_bfloat16 bf16;

// -------------------- scratch (__device__ globals, no allocs) --------------------
__device__ __align__(256) bf16  g_lat_h[BB * LAT],  g_lat_l[BB * LAT];
// ping-pong [h | x] buffers (read s&1, write (s+1)&1) — avoids cross-CTA WAR in fused step
__device__ __align__(256) bf16  g_hx_h [2 * BB * KCAT], g_hx_l [2 * BB * KCAT];
__device__ __align__(256) bf16  g_t1_h [BB * HH],   g_t1_l [BB * HH];
__device__ __align__(256) bf16  g_t2_h [BB * HH],   g_t2_l [BB * HH];
__device__ __align__(256) bf16  g_hall_h[(size_t)MALL * HH];
__device__ __align__(256) bf16  g_hall_l[(size_t)MALL * HH];
__device__ __align__(256) bf16  g_p1_h [(size_t)MALL * HH];
__device__ __align__(256) bf16  g_p1_l [(size_t)MALL * HH];
__device__ __align__(256) bf16  g_p2_h [(size_t)MALL * AA];
__device__ __align__(256) bf16  g_p2_l [(size_t)MALL * AA];
// precomputed n-gate input projection for all steps: inn[s*BB+b][j]
__device__ __align__(256) float g_inn  [(size_t)MALL * HH];
// all-step inputs x as split planes [MALL x 64]
__device__ __align__(256) bf16  g_x_h  [(size_t)MALL * AA], g_x_l[(size_t)MALL * AA];
// interleaved recurrent weight: row 3j+g <- [W_hh | W_ih(r,z) / 0(n)]
__device__ __align__(256) bf16  g_wc_h [NCAT * KCAT], g_wc_l [NCAT * KCAT];
__device__ __align__(256) bf16  g_win_h[HH * AA],     g_win_l[HH * AA];    // W_ih n-gate rows
__device__ __align__(256) bf16  g_wd1_h[HH * LAT],    g_wd1_l[HH * LAT];
__device__ __align__(256) bf16  g_wd2_h[HH * HH],     g_wd2_l[HH * HH];
__device__ __align__(256) bf16  g_wd3_h[HH * HH],     g_wd3_l[HH * HH];
__device__ __align__(256) bf16  g_wm1_h[HH * HH],     g_wm1_l[HH * HH];
__device__ __align__(256) bf16  g_wm2_h[AA * HH],     g_wm2_l[AA * HH];
__device__ __align__(256) bf16  g_wm3_h[AA * AA],     g_wm3_l[AA * AA];
__device__ __align__(256) float g_bcat[NCAT];          // interleaved triple bias

// -------------------- PTX helpers --------------------
__device__ __forceinline__ uint32_t smem_u32(const void* p) {
    return (uint32_t)__cvta_generic_to_shared(p);
}
__device__ __forceinline__ void cpasync16(uint32_t s, const void* g) {
    asm volatile("cp.async.cg.shared.global [%0], [%1], 16;\n" :: "r"(s), "l"(g));
}
__device__ __forceinline__ void ldmx4(uint32_t& r0, uint32_t& r1, uint32_t& r2, uint32_t& r3,
                                      uint32_t addr) {
    asm volatile("ldmatrix.sync.aligned.m8n8.x4.shared.b16 {%0,%1,%2,%3}, [%4];\n"
                 : "=r"(r0), "=r"(r1), "=r"(r2), "=r"(r3) : "r"(addr));
}
__device__ __forceinline__ void mma16816(float* c, const uint32_t* a, const uint32_t* b) {
    asm volatile(
        "mma.sync.aligned.m16n8k16.row.col.f32.bf16.bf16.f32 "
        "{%0,%1,%2,%3}, {%4,%5,%6,%7}, {%8,%9}, {%0,%1,%2,%3};\n"
        : "+f"(c[0]), "+f"(c[1]), "+f"(c[2]), "+f"(c[3])
        : "r"(a[0]), "r"(a[1]), "r"(a[2]), "r"(a[3]), "r"(b[0]), "r"(b[1]));
}
__device__ __forceinline__ void fsplit(float v, bf16& h, bf16& l) {
    h = __float2bfloat16(v);
    l = __float2bfloat16(v - __bfloat162float(h));
}
// 64B-row swizzle: chunk q = c ^ ((r>>1)&3) -> 8 consecutive rows hit 8 distinct bank groups
__device__ __forceinline__ uint32_t swz(int r, int c) {
    return (uint32_t)(r * 64 + ((c ^ ((r >> 1) & 3)) << 4));
}

// -------------------- mma.sync split-bf16 GEMM (generic) --------------------
// C[m,n] = act( sum_k A[m,k]*Bw[n,k] + bias[n] ); A,B as bf16 hi/lo planes.
// TERMS=3: acc = Ah*Bh + Ah*Bl + Al*Bh.  TERMS=2: acc = Ah*Bh + Ah*Bl (Alo unused/unloaded).
// BM=128, BK=32, BN template. M%128==0, K%32==0; N guarded via BN tile bound.
// act: 0 none, 1 tanh. omode: 0 fp32 C, 1 split bf16 planes, 2 fp32 scatter to out.
template<int BN, int TERMS>
__global__ void __launch_bounds__(256)
mma_gemm(const bf16* __restrict__ Ahi, const bf16* __restrict__ Alo,
         const bf16* __restrict__ Bhi, const bf16* __restrict__ Blo,
         const float* __restrict__ bias,
         float* __restrict__ Cf, bf16* __restrict__ Chi, bf16* __restrict__ Clo,
         int M, int N, int K, int ldc, int act, int omode)
{
    constexpr int WN  = BN / 2;
    constexpr int NT  = WN / 8;
    constexpr int NT2 = NT / 2;
    constexpr int A_BYTES = 128 * 64;
    constexpr int B_BYTES = BN * 64;
    constexpr int APL = (TERMS == 3) ? 2 : 1;            // A planes staged
    constexpr int STAGE   = APL * A_BYTES + 2 * B_BYTES;

    extern __shared__ char smem[];
    const uint32_t sbase = smem_u32(smem);
    const int tid = threadIdx.x;
    const int lane = tid & 31, wid = tid >> 5;
    const int wm = wid & 3, wn = wid >> 2;
    const int row0 = blockIdx.y * 128;
    const int col0 = blockIdx.x * BN;
    const int KT = K >> 5;

    float acc[2][NT][4];
#pragma unroll
    for (int t = 0; t < 2; t++)
#pragma unroll
        for (int n = 0; n < NT; n++)
#pragma unroll
            for (int i = 0; i < 4; i++) acc[t][n][i] = 0.f;

    auto load_stage = [&](int kt, int s) {
        const int k0 = kt << 5;
        const uint32_t so = sbase + s * STAGE;
#pragma unroll
        for (int i = 0; i < 2; i++) {
            int l = tid + i * 256;
            int r = l >> 2, c = l & 3;
            uint32_t sa = so + swz(r, c);
            size_t go = (size_t)(row0 + r) * K + k0 + c * 8;
            cpasync16(sa, Ahi + go);
            if (TERMS == 3) cpasync16(sa + A_BYTES, Alo + go);
        }
#pragma unroll
        for (int i = 0; i < (BN * 4 + 255) / 256; i++) {
            int l = tid + i * 256;
            if (l < BN * 4) {
                int r = l >> 2, c = l & 3;
                uint32_t sb = so + APL * A_BYTES + swz(r, c);
                size_t go = (size_t)(col0 + r) * K + k0 + c * 8;
                cpasync16(sb,           Bhi + go);
                cpasync16(sb + B_BYTES, Blo + go);
            }
        }
        asm volatile("cp.async.commit_group;\n" ::: "memory");
    };

    load_stage(0, 0);
    for (int kt = 0; kt < KT; kt++) {
        if (kt + 1 < KT) {
            load_stage(kt + 1, (kt + 1) & 1);
            asm volatile("cp.async.wait_group 1;\n" ::: "memory");
        } else {
            asm volatile("cp.async.wait_group 0;\n" ::: "memory");
        }
        __syncthreads();

        const uint32_t so = sbase + (kt & 1) * STAGE;
#pragma unroll
        for (int ks = 0; ks < 2; ks++) {
            uint32_t ah[2][4], al[2][4];
#pragma unroll
            for (int t = 0; t < 2; t++) {
                int r = wm * 32 + t * 16 + (lane & 7) + ((lane >> 3) & 1) * 8;
                int c = ks * 2 + (lane >> 4);
                uint32_t addr = so + swz(r, c);
                ldmx4(ah[t][0], ah[t][1], ah[t][2], ah[t][3], addr);
                if (TERMS == 3)
                    ldmx4(al[t][0], al[t][1], al[t][2], al[t][3], addr + A_BYTES);
            }
#pragma unroll
            for (int p = 0; p < NT2; p++) {
                int r = wn * WN + p * 16 + (lane & 7) + (lane >> 4) * 8;
                int c = ks * 2 + ((lane >> 3) & 1);
                uint32_t addr = so + APL * A_BYTES + swz(r, c);
                uint32_t bh[4], bl[4];
                ldmx4(bh[0], bh[1], bh[2], bh[3], addr);
                ldmx4(bl[0], bl[1], bl[2], bl[3], addr + B_BYTES);
#pragma unroll
                for (int t = 0; t < 2; t++) {
                    mma16816(acc[t][2 * p],     ah[t], bh);
                    mma16816(acc[t][2 * p],     ah[t], bl);
                    if (TERMS == 3) mma16816(acc[t][2 * p], al[t], bh);
                    mma16816(acc[t][2 * p + 1], ah[t], bh + 2);
                    mma16816(acc[t][2 * p + 1], ah[t], bl + 2);
                    if (TERMS == 3) mma16816(acc[t][2 * p + 1], al[t], bh + 2);
                }
            }
        }
        __syncthreads();
    }

#pragma unroll
    for (int t = 0; t < 2; t++) {
#pragma unroll
        for (int nt = 0; nt < NT; nt++) {
            int col = col0 + wn * WN + nt * 8 + (lane & 3) * 2;
            float b0 = bias[col], b1 = bias[col + 1];
#pragma unroll
            for (int h = 0; h < 2; h++) {
                int m = row0 + wm * 32 + t * 16 + (lane >> 2) + h * 8;
                float vx = acc[t][nt][2 * h + 0] + b0;
                float vy = acc[t][nt][2 * h + 1] + b1;
                if (act) { vx = tanhf(vx); vy = tanhf(vy); }
                if (omode == 0) {
                    size_t idx = (size_t)m * ldc + col;
                    Cf[idx] = vx; Cf[idx + 1] = vy;
                } else if (omode == 1) {
                    size_t idx = (size_t)m * ldc + col;
                    bf16 hx, lx; fsplit(vx, hx, lx);
                    bf16 hy, ly; fsplit(vy, hy, ly);
                    Chi[idx] = hx; Chi[idx + 1] = hy;
                    Clo[idx] = lx; Clo[idx + 1] = ly;
                } else {
                    int b = m & (BB - 1), s = m >> 12;
                    size_t idx = (size_t)b * (LL * AA) + (size_t)(s + 1) * AA + col;
                    Cf[idx] = vx; Cf[idx + 1] = vy;
                }
            }
        }
    }
}

// -------------------- fused GRU step: GEMM (interleaved triples) + gates --------------------
// A = [h|x] read buffer (planes), B = interleaved wcat' (row 3j+g). BN=96 so each
// CTA owns complete (r,z,n) triples. Epilogue stages O tile in smem, applies the
// GRU gate math using precomputed inn, writes h_new to hall + write hx buffer.
#define ST_A 8192                  // 128 rows x 64B (one A plane, BK=32)
#define ST_B 6144                  // 96 rows x 64B
#define ST_STAGE (2 * ST_A + 2 * ST_B)       // 28672
#define ST_SMEM  (2 * ST_STAGE)              // 57344 (>= O tile 128*97*4=49664)
#define ROWF 97

__global__ void __launch_bounds__(256)
step_kernel(const bf16* __restrict__ Ahi, const bf16* __restrict__ Alo,   // read hx buffer
            const bf16* __restrict__ Bhi, const bf16* __restrict__ Blo,   // wcat' planes
            const float* __restrict__ bias,                               // bcat'
            const float* __restrict__ inn_s,                              // + s*BB*HH
            const float* __restrict__ target,
            bf16* __restrict__ hxw_h, bf16* __restrict__ hxw_l,           // write hx buffer
            bf16* __restrict__ hall_h, bf16* __restrict__ hall_l,         // + s*BB*HH
            int s)
{
    constexpr int NT = 6, NT2 = 3, WN = 48;
    extern __shared__ char smem[];
    float* sO = (float*)smem;
    const uint32_t sbase = smem_u32(smem);
    const int tid = threadIdx.x;
    const int lane = tid & 31, wid = tid >> 5;
    const int wm = wid & 3, wn = wid >> 2;
    const int row0 = blockIdx.y * 128;
    const int col0 = blockIdx.x * 96;
    const int KT = KCAT >> 5;   // 18

    float acc[2][NT][4];
#pragma unroll
    for (int t = 0; t < 2; t++)
#pragma unroll
        for (int n = 0; n < NT; n++)
#pragma unroll
            for (int i = 0; i < 4; i++) acc[t][n][i] = 0.f;

    auto load_stage = [&](int kt, int st) {
        const int k0 = kt << 5;
        const uint32_t so = sbase + st * ST_STAGE;
#pragma unroll
        for (int i = 0; i < 2; i++) {                  // A: 512 chunk-loads
            int l = tid + i * 256;
            int r = l >> 2, c = l & 3;
            uint32_t sa = so + swz(r, c);
            size_t go = (size_t)(row0 + r) * KCAT + k0 + c * 8;
            cpasync16(sa,        Ahi + go);
            cpasync16(sa + ST_A, Alo + go);
        }
#pragma unroll
        for (int i = 0; i < 2; i++) {                  // B: 384 chunk-loads
            int l = tid + i * 256;
            if (l < 384) {
                int r = l >> 2, c = l & 3;
                uint32_t sb = so + 2 * ST_A + swz(r, c);
                size_t go = (size_t)(col0 + r) * KCAT + k0 + c * 8;
                cpasync16(sb,        Bhi + go);
                cpasync16(sb + ST_B, Blo + go);
            }
        }
        asm volatile("cp.async.commit_group;\n" ::: "memory");
    };

    load_stage(0, 0);
    for (int kt = 0; kt < KT; kt++) {
        if (kt + 1 < KT) {
            load_stage(kt + 1, (kt + 1) & 1);
            asm volatile("cp.async.wait_group 1;\n" ::: "memory");
        } else {
            asm volatile("cp.async.wait_group 0;\n" ::: "memory");
        }
        __syncthreads();

        const uint32_t so = sbase + (kt & 1) * ST_STAGE;
#pragma unroll
        for (int ks = 0; ks < 2; ks++) {
            uint32_t ah[2][4], al[2][4];
#pragma unroll
            for (int t = 0; t < 2; t++) {
                int r = wm * 32 + t * 16 + (lane & 7) + ((lane >> 3) & 1) * 8;
                int c = ks * 2 + (lane >> 4);
                uint32_t addr = so + swz(r, c);
                ldmx4(ah[t][0], ah[t][1], ah[t][2], ah[t][3], addr);
                ldmx4(al[t][0], al[t][1], al[t][2], al[t][3], addr + ST_A);
            }
#pragma unroll
            for (int p = 0; p < NT2; p++) {
                int r = wn * WN + p * 16 + (lane & 7) + (lane >> 4) * 8;
                int c = ks * 2 + ((lane >> 3) & 1);
                uint32_t addr = so + 2 * ST_A + swz(r, c);
                uint32_t bh[4], bl[4];
                ldmx4(bh[0], bh[1], bh[2], bh[3], addr);
                ldmx4(bl[0], bl[1], bl[2], bl[3], addr + ST_B);
#pragma unroll
                for (int t = 0; t < 2; t++) {
                    mma16816(acc[t][2 * p],     ah[t], bh);
                    mma16816(acc[t][2 * p],     ah[t], bl);
                    mma16816(acc[t][2 * p],     al[t], bh);
                    mma16816(acc[t][2 * p + 1], ah[t], bh + 2);
                    mma16816(acc[t][2 * p + 1], ah[t], bl + 2);
                    mma16816(acc[t][2 * p + 1], al[t], bh + 2);
                }
            }
        }
        __syncthreads();
    }

    // stage O tile (+bias) to smem
#pragma unroll
    for (int t = 0; t < 2; t++) {
#pragma unroll
        for (int nt = 0; nt < NT; nt++) {
            int col = wn * WN + nt * 8 + (lane & 3) * 2;
            float b0 = bias[col0 + col], b1 = bias[col0 + col + 1];
#pragma unroll
            for (int h = 0; h < 2; h++) {
                int r = wm * 32 + t * 16 + (lane >> 2) + h * 8;
                sO[r * ROWF + col]     = acc[t][nt][2 * h + 0] + b0;
                sO[r * ROWF + col + 1] = acc[t][nt][2 * h + 1] + b1;
            }
        }
    }
    __syncthreads();

    // gate phase: 128 rows x 32 triples per CTA, 16 items/thread.
    // COALESCED mapping: j fast (32 consecutive threads -> 32 consecutive hidden
    // indices at one batch row). R10 had r-fast here -> every global access hit
    // its own 32B sector (~460MB/step); that was the entire 9.9ms regression.
#pragma unroll
    for (int it = 0; it < 16; it++) {
        int idx = tid + it * 256;
        int j = idx & 31, r = idx >> 5;        // j in 0..31, r in 0..127
        int b = row0 + r;
        int jg = blockIdx.x * 32 + j;          // global hidden index
        float o_r  = sO[r * ROWF + 3 * j];
        float o_z  = sO[r * ROWF + 3 * j + 1];
        float o_hn = sO[r * ROWF + 3 * j + 2];
        float innv = inn_s[(size_t)b * HH + jg];
        size_t hxi = (size_t)b * KCAT + jg;
        float hp = __bfloat162float(Ahi[hxi]) + __bfloat162float(Alo[hxi]);
        float rg = 1.f / (1.f + expf(-o_r));
        float zg = 1.f / (1.f + expf(-o_z));
        float n  = tanhf(innv + rg * o_hn);
        float hv = (1.f - zg) * n + zg * hp;
        bf16 hh, hl; fsplit(hv, hh, hl);
        hall_h[(size_t)b * HH + jg] = hh;
        hall_l[(size_t)b * HH + jg] = hl;
        hxw_h[hxi] = hh;
        hxw_l[hxi] = hl;
        // stage next x into the WRITE buffer (one writer per (b,a): jg<64)
        if (jg < AA && s < NSTEP - 1) {
            float xv = target[(size_t)b * (LL * AA) + (size_t)(s + 1) * AA + jg];
            bf16 xh, xl; fsplit(xv, xh, xl);
            hxw_h[(size_t)b * KCAT + HH + jg] = xh;
            hxw_l[(size_t)b * KCAT + HH + jg] = xl;
        }
    }
}

// -------------------- prep: interleaved wcat' + bias' + W_ihn planes --------------------
__global__ void prep_kernel(const float* __restrict__ W_hh, const float* __restrict__ W_ih,
                            const float* __restrict__ b_hh, const float* __restrict__ b_ih)
{
    int i = blockIdx.x * blockDim.x + threadIdx.x;
    if (i < NCAT * KCAT) {
        int n = i / KCAT, k = i % KCAT;
        int g = n % 3, jj = n / 3;             // interleaved row 3j+g
        int src = g * HH + jj;
        float v;
        if (k < HH)     v = W_hh[(size_t)src * HH + k];
        else if (g < 2) v = W_ih[(size_t)src * AA + (k - HH)];
        else            v = 0.f;               // n-gate x-part handled via precomputed inn
        fsplit(v, g_wc_h[i], g_wc_l[i]);
    }
    if (i < NCAT) {
        int g = i % 3, jj = i / 3;
        int src = g * HH + jj;
        g_bcat[i] = b_hh[src] + ((g < 2) ? b_ih[src] : 0.f);
    }
    if (i < HH * AA) {
        fsplit(W_ih[(size_t)(2 * HH) * AA + i], g_win_h[i], g_win_l[i]);
    }
}

// -------------------- split / xall / bos --------------------
__global__ void split_kernel(const float* __restrict__ src, bf16* __restrict__ hi,
                             bf16* __restrict__ lo, int n)
{
    int i = blockIdx.x * blockDim.x + threadIdx.x;
    if (i < n) fsplit(src[i], hi[i], lo[i]);
}

__global__ void xall_kernel(const float* __restrict__ target)
{
    int idx = blockIdx.x * blockDim.x + threadIdx.x;     // MALL*AA items
    if (idx >= MALL * AA) return;
    int m = idx >> 6, a = idx & 63;
    int s = m >> 12, b = m & (BB - 1);
    float v = (s == 0) ? ((a == 0) ? 16.f : -16.f)
                       : target[(size_t)b * (LL * AA) + (size_t)s * AA + a];
    fsplit(v, g_x_h[idx], g_x_l[idx]);
}

__global__ void bos_kernel(float* __restrict__ out)
{
    int i = blockIdx.x * blockDim.x + threadIdx.x;
    if (i >= BB * AA) return;
    int b = i >> 6, a = i & 63;
    float v = (a == 0) ? 16.f : -16.f;
    out[(size_t)b * (LL * AA) + a] = v;
    g_hx_h[(size_t)b * KCAT + HH + a] = __float2bfloat16(v);   // buffer 0 x-part (exact)
    g_hx_l[(size_t)b * KCAT + HH + a] = __float2bfloat16(0.f);
}

// -------------------- launch --------------------
extern "C" void kernel_launch(void* const* d_in, const int* in_sizes, int n_in,
                              void* d_out, int out_size)
{
    const float* latent = (const float*)d_in[0];
    const float* target = (const float*)d_in[1];
    const float* Wd1 = (const float*)d_in[2];
    const float* bd1 = (const float*)d_in[3];
    const float* Wd2 = (const float*)d_in[4];
    const float* bd2 = (const float*)d_in[5];
    const float* Wd3 = (const float*)d_in[6];
    const float* bd3 = (const float*)d_in[7];
    const float* W_ih = (const float*)d_in[8];
    const float* W_hh = (const float*)d_in[9];
    const float* b_ih = (const float*)d_in[10];
    const float* b_hh = (const float*)d_in[11];
    const float* Wm1 = (const float*)d_in[12];
    const float* bm1 = (const float*)d_in[13];
    const float* Wm2 = (const float*)d_in[14];
    const float* bm2 = (const float*)d_in[15];
    const float* Wm3 = (const float*)d_in[16];
    const float* bm3 = (const float*)d_in[17];
    float* out = (float*)d_out;

    bf16 *lath, *latl, *hxh, *hxl, *t1h, *t1l, *t2h, *t2l;
    bf16 *hallh, *halll, *p1h, *p1l, *p2h, *p2l, *xh, *xl;
    bf16 *wch, *wcl, *winh, *winl, *wd1h, *wd1l, *wd2h, *wd2l, *wd3h, *wd3l;
    bf16 *wm1h, *wm1l, *wm2h, *wm2l, *wm3h, *wm3l;
    float *inn, *bcat;
    cudaGetSymbolAddress((void**)&lath, g_lat_h);  cudaGetSymbolAddress((void**)&latl, g_lat_l);
    cudaGetSymbolAddress((void**)&hxh,  g_hx_h);   cudaGetSymbolAddress((void**)&hxl,  g_hx_l);
    cudaGetSymbolAddress((void**)&t1h,  g_t1_h);   cudaGetSymbolAddress((void**)&t1l,  g_t1_l);
    cudaGetSymbolAddress((void**)&t2h,  g_t2_h);   cudaGetSymbolAddress((void**)&t2l,  g_t2_l);
    cudaGetSymbolAddress((void**)&hallh,g_hall_h); cudaGetSymbolAddress((void**)&halll,g_hall_l);
    cudaGetSymbolAddress((void**)&p1h,  g_p1_h);   cudaGetSymbolAddress((void**)&p1l,  g_p1_l);
    cudaGetSymbolAddress((void**)&p2h,  g_p2_h);   cudaGetSymbolAddress((void**)&p2l,  g_p2_l);
    cudaGetSymbolAddress((void**)&xh,   g_x_h);    cudaGetSymbolAddress((void**)&xl,   g_x_l);
    cudaGetSymbolAddress((void**)&wch,  g_wc_h);   cudaGetSymbolAddress((void**)&wcl,  g_wc_l);
    cudaGetSymbolAddress((void**)&winh, g_win_h);  cudaGetSymbolAddress((void**)&winl, g_win_l);
    cudaGetSymbolAddress((void**)&wd1h, g_wd1_h);  cudaGetSymbolAddress((void**)&wd1l, g_wd1_l);
    cudaGetSymbolAddress((void**)&wd2h, g_wd2_h);  cudaGetSymbolAddress((void**)&wd2l, g_wd2_l);
    cudaGetSymbolAddress((void**)&wd3h, g_wd3_h);  cudaGetSymbolAddress((void**)&wd3l, g_wd3_l);
    cudaGetSymbolAddress((void**)&wm1h, g_wm1_h);  cudaGetSymbolAddress((void**)&wm1l, g_wm1_l);
    cudaGetSymbolAddress((void**)&wm2h, g_wm2_h);  cudaGetSymbolAddress((void**)&wm2l, g_wm2_l);
    cudaGetSymbolAddress((void**)&wm3h, g_wm3_h);  cudaGetSymbolAddress((void**)&wm3l, g_wm3_l);
    cudaGetSymbolAddress((void**)&inn,  g_inn);
    cudaGetSymbolAddress((void**)&bcat, g_bcat);

    const int SM128_3 = 2 * (2 * 128 * 64 + 2 * 128 * 64);   // 65536
    const int SM128_2 = 2 * (1 * 128 * 64 + 2 * 128 * 64);   // 49152
    const int SM64_2  = 2 * (1 * 128 * 64 + 2 *  64 * 64);   // 32768
    cudaFuncSetAttribute(mma_gemm<128,3>, cudaFuncAttributeMaxDynamicSharedMemorySize, SM128_3);
    cudaFuncSetAttribute(mma_gemm<128,2>, cudaFuncAttributeMaxDynamicSharedMemorySize, SM128_2);
    cudaFuncSetAttribute(mma_gemm<64,2>,  cudaFuncAttributeMaxDynamicSharedMemorySize, SM64_2);
    cudaFuncSetAttribute(step_kernel,     cudaFuncAttributeMaxDynamicSharedMemorySize, ST_SMEM);

    // weight prep + input staging
    prep_kernel<<<(NCAT * KCAT + 255) / 256, 256>>>(W_hh, W_ih, b_hh, b_ih);
    split_kernel<<<(HH * LAT + 255) / 256, 256>>>(Wd1, wd1h, wd1l, HH * LAT);
    split_kernel<<<(HH * HH + 255) / 256, 256>>>(Wd2, wd2h, wd2l, HH * HH);
    split_kernel<<<(HH * HH + 255) / 256, 256>>>(Wd3, wd3h, wd3l, HH * HH);
    split_kernel<<<(HH * HH + 255) / 256, 256>>>(Wm1, wm1h, wm1l, HH * HH);
    split_kernel<<<(AA * HH + 255) / 256, 256>>>(Wm2, wm2h, wm2l, AA * HH);
    split_kernel<<<(AA * AA + 255) / 256, 256>>>(Wm3, wm3h, wm3l, AA * AA);
    split_kernel<<<(BB * LAT + 255) / 256, 256>>>(latent, lath, latl, BB * LAT);
    xall_kernel<<<(MALL * AA + 255) / 256, 256>>>(target);
    bos_kernel<<<(BB * AA + 255) / 256, 256>>>(out);

    // precompute inn[s,b,j] = x_s . W_ihn + b_ihn for ALL steps (one GEMM, 3-term:
    // feeds the recurrence, keep full precision)
    mma_gemm<128,3><<<dim3(HH / 128, MALL / 128), 256, SM128_3>>>(
        xh, xl, winh, winl, b_ih + 2 * HH, inn, nullptr, nullptr,
        MALL, HH, AA, HH, 0, 0);

    // initial hidden -> hx buffer 0 (3-term: feeds the recurrence)
    mma_gemm<128,3><<<dim3(HH / 128, BB / 128), 256, SM128_3>>>(
        lath, latl, wd1h, wd1l, bd1, nullptr, t1h, t1l, BB, HH, LAT, HH, 1, 1);
    mma_gemm<128,3><<<dim3(HH / 128, BB / 128), 256, SM128_3>>>(
        t1h, t1l, wd2h, wd2l, bd2, nullptr, t2h, t2l, BB, HH, HH, HH, 1, 1);
    mma_gemm<128,3><<<dim3(HH / 128, BB / 128), 256, SM128_3>>>(
        t2h, t2l, wd3h, wd3l, bd3, nullptr, hxh, hxl, BB, HH, HH, KCAT, 0, 1);

    // sequential GRU core: fused GEMM+gates, ping-pong hx buffers
    for (int s = 0; s < NSTEP; s++) {
        const size_t rb = (size_t)(s & 1) * BB * KCAT;
        const size_t wb = (size_t)((s + 1) & 1) * BB * KCAT;
        step_kernel<<<dim3(NCAT / 96, BB / 128), 256, ST_SMEM>>>(
            hxh + rb, hxl + rb, wch, wcl, bcat,
            inn + (size_t)s * BB * HH, target,
            hxh + wb, hxl + wb,
            hallh + (size_t)s * BB * HH, halll + (size_t)s * BB * HH, s);
    }

    // deferred prediction head — output-facing, 2-term split (error ~1e-5, not
    // amplified by the recurrence; skips Alo load + 1/3 of MMAs)
    mma_gemm<128,2><<<dim3(HH / 128, MALL / 128), 256, SM128_2>>>(
        hallh, nullptr, wm1h, wm1l, bm1, nullptr, p1h, p1l, MALL, HH, HH, HH, 1, 1);
    mma_gemm<64,2><<<dim3(1, MALL / 128), 256, SM64_2>>>(
        p1h, nullptr, wm2h, wm2l, bm2, nullptr, p2h, p2l, MALL, AA, HH, AA, 1, 1);
    mma_gemm<64,2><<<dim3(1, MALL / 128), 256, SM64_2>>>(
        p2h, nullptr, wm3h, wm3l, bm3, out, nullptr, nullptr, MALL, AA, AA, 0, 0, 2);
}

// round 14
// speedup vs baseline: 2.2546x; 1.1915x over previous
#include <cuda_runtime.h>
#include <cuda_bf16.h>
#include <cstddef>
#include <cstdint>

// Problem constants
#define BB    4096      // batch
#define LAT   256
#define HH    512
#define AA    64
#define LL    128
#define NSTEP 127       // L-1 sequential GRU steps
#define KCAT  576       // H + A
#define NCAT  1536      // 3H
#define MALL  (NSTEP * BB)   // 520192 rows

typedef __nv_bfloat16 bf16;

// -------------------- scratch (__device__ globals, no allocs) --------------------
__device__ __align__(256) bf16  g_lat_h[BB * LAT],  g_lat_l[BB * LAT];
// ping-pong [h | x] buffers (read s&1, write (s+1)&1) — avoids cross-CTA WAR in fused step
__device__ __align__(256) bf16  g_hx_h [2 * BB * KCAT], g_hx_l [2 * BB * KCAT];
__device__ __align__(256) bf16  g_t1_h [BB * HH],   g_t1_l [BB * HH];
__device__ __align__(256) bf16  g_t2_h [BB * HH],   g_t2_l [BB * HH];
__device__ __align__(256) bf16  g_hall_h[(size_t)MALL * HH];   // hi only: pred head is 2-term
__device__ __align__(256) bf16  g_p1_h [(size_t)MALL * HH];
__device__ __align__(256) bf16  g_p2_h [(size_t)MALL * AA];
// precomputed n-gate input projection for all steps: inn[s*BB+b][j]
__device__ __align__(256) float g_inn  [(size_t)MALL * HH];
// all-step inputs x as split planes [MALL x 64]
__device__ __align__(256) bf16  g_x_h  [(size_t)MALL * AA], g_x_l[(size_t)MALL * AA];
// interleaved recurrent weight: row 3j+g <- [W_hh | W_ih(r,z) / 0(n)]
__device__ __align__(256) bf16  g_wc_h [NCAT * KCAT], g_wc_l [NCAT * KCAT];
__device__ __align__(256) bf16  g_win_h[HH * AA],     g_win_l[HH * AA];    // W_ih n-gate rows
__device__ __align__(256) bf16  g_wd1_h[HH * LAT],    g_wd1_l[HH * LAT];
__device__ __align__(256) bf16  g_wd2_h[HH * HH],     g_wd2_l[HH * HH];
__device__ __align__(256) bf16  g_wd3_h[HH * HH],     g_wd3_l[HH * HH];
__device__ __align__(256) bf16  g_wm1_h[HH * HH],     g_wm1_l[HH * HH];
__device__ __align__(256) bf16  g_wm2_h[AA * HH],     g_wm2_l[AA * HH];
__device__ __align__(256) bf16  g_wm3_h[AA * AA],     g_wm3_l[AA * AA];
__device__ __align__(256) float g_bcat[NCAT];          // interleaved triple bias

// -------------------- PTX helpers --------------------
__device__ __forceinline__ uint32_t smem_u32(const void* p) {
    return (uint32_t)__cvta_generic_to_shared(p);
}
__device__ __forceinline__ void cpasync16(uint32_t s, const void* g) {
    asm volatile("cp.async.cg.shared.global [%0], [%1], 16;\n" :: "r"(s), "l"(g));
}
__device__ __forceinline__ void ldmx4(uint32_t& r0, uint32_t& r1, uint32_t& r2, uint32_t& r3,
                                      uint32_t addr) {
    asm volatile("ldmatrix.sync.aligned.m8n8.x4.shared.b16 {%0,%1,%2,%3}, [%4];\n"
                 : "=r"(r0), "=r"(r1), "=r"(r2), "=r"(r3) : "r"(addr));
}
__device__ __forceinline__ void mma16816(float* c, const uint32_t* a, const uint32_t* b) {
    asm volatile(
        "mma.sync.aligned.m16n8k16.row.col.f32.bf16.bf16.f32 "
        "{%0,%1,%2,%3}, {%4,%5,%6,%7}, {%8,%9}, {%0,%1,%2,%3};\n"
        : "+f"(c[0]), "+f"(c[1]), "+f"(c[2]), "+f"(c[3])
        : "r"(a[0]), "r"(a[1]), "r"(a[2]), "r"(a[3]), "r"(b[0]), "r"(b[1]));
}
__device__ __forceinline__ void fsplit(float v, bf16& h, bf16& l) {
    h = __float2bfloat16(v);
    l = __float2bfloat16(v - __bfloat162float(h));
}
// 64B-row swizzle (mma_gemm, BK=32): chunk q = c ^ ((r>>1)&3)
__device__ __forceinline__ uint32_t swz(int r, int c) {
    return (uint32_t)(r * 64 + ((c ^ ((r >> 1) & 3)) << 4));
}
// 128B-row swizzle (step_kernel, BK=64): chunk q = c ^ (r&7) -> 8 rows, 8 distinct
// 16B bank-groups; conflict-free LDSM (standard SW128 pattern).
__device__ __forceinline__ uint32_t swz128(int r, int c) {
    return (uint32_t)(r * 128 + ((c ^ (r & 7)) << 4));
}

// -------------------- mma.sync split-bf16 GEMM (generic) --------------------
// C[m,n] = act( sum_k A[m,k]*Bw[n,k] + bias[n] ); A,B as bf16 hi/lo planes.
// TERMS=3: acc = Ah*Bh + Ah*Bl + Al*Bh.  TERMS=2: acc = Ah*Bh + Ah*Bl (Alo unused).
// BM=128, BK=32, BN template. M%128==0, K%32==0.
// act: 0 none, 1 tanh.
// omode: 0 fp32 C, 1 split bf16 planes, 2 fp32 scatter to out, 3 bf16 hi plane only.
template<int BN, int TERMS>
__global__ void __launch_bounds__(256)
mma_gemm(const bf16* __restrict__ Ahi, const bf16* __restrict__ Alo,
         const bf16* __restrict__ Bhi, const bf16* __restrict__ Blo,
         const float* __restrict__ bias,
         float* __restrict__ Cf, bf16* __restrict__ Chi, bf16* __restrict__ Clo,
         int M, int N, int K, int ldc, int act, int omode)
{
    constexpr int WN  = BN / 2;
    constexpr int NT  = WN / 8;
    constexpr int NT2 = NT / 2;
    constexpr int A_BYTES = 128 * 64;
    constexpr int B_BYTES = BN * 64;
    constexpr int APL = (TERMS == 3) ? 2 : 1;            // A planes staged
    constexpr int STAGE   = APL * A_BYTES + 2 * B_BYTES;

    extern __shared__ char smem[];
    const uint32_t sbase = smem_u32(smem);
    const int tid = threadIdx.x;
    const int lane = tid & 31, wid = tid >> 5;
    const int wm = wid & 3, wn = wid >> 2;
    const int row0 = blockIdx.y * 128;
    const int col0 = blockIdx.x * BN;
    const int KT = K >> 5;

    float acc[2][NT][4];
#pragma unroll
    for (int t = 0; t < 2; t++)
#pragma unroll
        for (int n = 0; n < NT; n++)
#pragma unroll
            for (int i = 0; i < 4; i++) acc[t][n][i] = 0.f;

    auto load_stage = [&](int kt, int s) {
        const int k0 = kt << 5;
        const uint32_t so = sbase + s * STAGE;
#pragma unroll
        for (int i = 0; i < 2; i++) {
            int l = tid + i * 256;
            int r = l >> 2, c = l & 3;
            uint32_t sa = so + swz(r, c);
            size_t go = (size_t)(row0 + r) * K + k0 + c * 8;
            cpasync16(sa, Ahi + go);
            if (TERMS == 3) cpasync16(sa + A_BYTES, Alo + go);
        }
#pragma unroll
        for (int i = 0; i < (BN * 4 + 255) / 256; i++) {
            int l = tid + i * 256;
            if (l < BN * 4) {
                int r = l >> 2, c = l & 3;
                uint32_t sb = so + APL * A_BYTES + swz(r, c);
                size_t go = (size_t)(col0 + r) * K + k0 + c * 8;
                cpasync16(sb,           Bhi + go);
                cpasync16(sb + B_BYTES, Blo + go);
            }
        }
        asm volatile("cp.async.commit_group;\n" ::: "memory");
    };

    load_stage(0, 0);
    for (int kt = 0; kt < KT; kt++) {
        if (kt + 1 < KT) {
            load_stage(kt + 1, (kt + 1) & 1);
            asm volatile("cp.async.wait_group 1;\n" ::: "memory");
        } else {
            asm volatile("cp.async.wait_group 0;\n" ::: "memory");
        }
        __syncthreads();

        const uint32_t so = sbase + (kt & 1) * STAGE;
#pragma unroll
        for (int ks = 0; ks < 2; ks++) {
            uint32_t ah[2][4], al[2][4];
#pragma unroll
            for (int t = 0; t < 2; t++) {
                int r = wm * 32 + t * 16 + (lane & 7) + ((lane >> 3) & 1) * 8;
                int c = ks * 2 + (lane >> 4);
                uint32_t addr = so + swz(r, c);
                ldmx4(ah[t][0], ah[t][1], ah[t][2], ah[t][3], addr);
                if (TERMS == 3)
                    ldmx4(al[t][0], al[t][1], al[t][2], al[t][3], addr + A_BYTES);
            }
#pragma unroll
            for (int p = 0; p < NT2; p++) {
                int r = wn * WN + p * 16 + (lane & 7) + (lane >> 4) * 8;
                int c = ks * 2 + ((lane >> 3) & 1);
                uint32_t addr = so + APL * A_BYTES + swz(r, c);
                uint32_t bh[4], bl[4];
                ldmx4(bh[0], bh[1], bh[2], bh[3], addr);
                ldmx4(bl[0], bl[1], bl[2], bl[3], addr + B_BYTES);
#pragma unroll
                for (int t = 0; t < 2; t++) {
                    mma16816(acc[t][2 * p],     ah[t], bh);
                    mma16816(acc[t][2 * p],     ah[t], bl);
                    if (TERMS == 3) mma16816(acc[t][2 * p], al[t], bh);
                    mma16816(acc[t][2 * p + 1], ah[t], bh + 2);
                    mma16816(acc[t][2 * p + 1], ah[t], bl + 2);
                    if (TERMS == 3) mma16816(acc[t][2 * p + 1], al[t], bh + 2);
                }
            }
        }
        __syncthreads();
    }

#pragma unroll
    for (int t = 0; t < 2; t++) {
#pragma unroll
        for (int nt = 0; nt < NT; nt++) {
            int col = col0 + wn * WN + nt * 8 + (lane & 3) * 2;
            float b0 = bias[col], b1 = bias[col + 1];
#pragma unroll
            for (int h = 0; h < 2; h++) {
                int m = row0 + wm * 32 + t * 16 + (lane >> 2) + h * 8;
                float vx = acc[t][nt][2 * h + 0] + b0;
                float vy = acc[t][nt][2 * h + 1] + b1;
                if (act) { vx = tanhf(vx); vy = tanhf(vy); }
                if (omode == 0) {
                    size_t idx = (size_t)m * ldc + col;
                    Cf[idx] = vx; Cf[idx + 1] = vy;
                } else if (omode == 1) {
                    size_t idx = (size_t)m * ldc + col;
                    bf16 hx, lx; fsplit(vx, hx, lx);
                    bf16 hy, ly; fsplit(vy, hy, ly);
                    Chi[idx] = hx; Chi[idx + 1] = hy;
                    Clo[idx] = lx; Clo[idx + 1] = ly;
                } else if (omode == 3) {
                    // hi-plane only (consumer is 2-term; lo plane would be dead)
                    size_t idx = (size_t)m * ldc + col;
                    __nv_bfloat162 th;
                    th.x = __float2bfloat16(vx); th.y = __float2bfloat16(vy);
                    *(__nv_bfloat162*)(Chi + idx) = th;
                } else {
                    int b = m & (BB - 1), s = m >> 12;
                    size_t idx = (size_t)b * (LL * AA) + (size_t)(s + 1) * AA + col;
                    Cf[idx] = vx; Cf[idx + 1] = vy;
                }
            }
        }
    }
}

// -------------------- fused GRU step: GEMM (interleaved triples) + gates --------------------
// BK=64 (halves __syncthreads: 36 -> 18 per step) with SW128 swizzle.
// A = [h|x] read buffer (planes), B = interleaved wcat' (row 3j+g). BN=96 so each
// CTA owns complete (r,z,n) triples. Epilogue stages O tile in smem, applies the
// GRU gate math using precomputed inn, writes h_new to hall_h + write hx buffer.
#define ST_A 16384                 // 128 rows x 128B (one A plane, BK=64)
#define ST_B 12288                 // 96 rows x 128B
#define ST_STAGE (2 * ST_A + 2 * ST_B)       // 57344
#define ST_SMEM  (2 * ST_STAGE)              // 114688 (sO 128*97*4=49664 aliases)
#define ROWF 97

__global__ void __launch_bounds__(256)
step_kernel(const bf16* __restrict__ Ahi, const bf16* __restrict__ Alo,   // read hx buffer
            const bf16* __restrict__ Bhi, const bf16* __restrict__ Blo,   // wcat' planes
            const float* __restrict__ bias,                               // bcat'
            const float* __restrict__ inn_s,                              // + s*BB*HH
            const float* __restrict__ target,
            bf16* __restrict__ hxw_h, bf16* __restrict__ hxw_l,           // write hx buffer
            bf16* __restrict__ hall_h,                                    // + s*BB*HH
            int s)
{
    constexpr int NT = 6, NT2 = 3, WN = 48;
    extern __shared__ char smem[];
    float* sO = (float*)smem;
    const uint32_t sbase = smem_u32(smem);
    const int tid = threadIdx.x;
    const int lane = tid & 31, wid = tid >> 5;
    const int wm = wid & 3, wn = wid >> 2;
    const int row0 = blockIdx.y * 128;
    const int col0 = blockIdx.x * 96;
    const int KT = KCAT >> 6;   // 9

    float acc[2][NT][4];
#pragma unroll
    for (int t = 0; t < 2; t++)
#pragma unroll
        for (int n = 0; n < NT; n++)
#pragma unroll
            for (int i = 0; i < 4; i++) acc[t][n][i] = 0.f;

    auto load_stage = [&](int kt, int st) {
        const int k0 = kt << 6;
        const uint32_t so = sbase + st * ST_STAGE;
#pragma unroll
        for (int i = 0; i < 4; i++) {                  // A: 1024 chunk-loads x 2 planes
            int l = tid + i * 256;                     // 0..1023
            int r = l >> 3, c = l & 7;
            uint32_t sa = so + swz128(r, c);
            size_t go = (size_t)(row0 + r) * KCAT + k0 + c * 8;
            cpasync16(sa,        Ahi + go);
            cpasync16(sa + ST_A, Alo + go);
        }
#pragma unroll
        for (int i = 0; i < 3; i++) {                  // B: 768 chunk-loads x 2 planes
            int l = tid + i * 256;                     // 0..767
            int r = l >> 3, c = l & 7;
            uint32_t sb = so + 2 * ST_A + swz128(r, c);
            size_t go = (size_t)(col0 + r) * KCAT + k0 + c * 8;
            cpasync16(sb,        Bhi + go);
            cpasync16(sb + ST_B, Blo + go);
        }
        asm volatile("cp.async.commit_group;\n" ::: "memory");
    };

    load_stage(0, 0);
    for (int kt = 0; kt < KT; kt++) {
        if (kt + 1 < KT) {
            load_stage(kt + 1, (kt + 1) & 1);
            asm volatile("cp.async.wait_group 1;\n" ::: "memory");
        } else {
            asm volatile("cp.async.wait_group 0;\n" ::: "memory");
        }
        __syncthreads();

        const uint32_t so = sbase + (kt & 1) * ST_STAGE;
#pragma unroll
        for (int ks = 0; ks < 4; ks++) {
            uint32_t ah[2][4], al[2][4];
#pragma unroll
            for (int t = 0; t < 2; t++) {
                int r = wm * 32 + t * 16 + (lane & 7) + ((lane >> 3) & 1) * 8;
                int c = ks * 2 + (lane >> 4);
                uint32_t addr = so + swz128(r, c);
                ldmx4(ah[t][0], ah[t][1], ah[t][2], ah[t][3], addr);
                ldmx4(al[t][0], al[t][1], al[t][2], al[t][3], addr + ST_A);
            }
#pragma unroll
            for (int p = 0; p < NT2; p++) {
                int r = wn * WN + p * 16 + (lane & 7) + (lane >> 4) * 8;
                int c = ks * 2 + ((lane >> 3) & 1);
                uint32_t addr = so + 2 * ST_A + swz128(r, c);
                uint32_t bh[4], bl[4];
                ldmx4(bh[0], bh[1], bh[2], bh[3], addr);
                ldmx4(bl[0], bl[1], bl[2], bl[3], addr + ST_B);
#pragma unroll
                for (int t = 0; t < 2; t++) {
                    mma16816(acc[t][2 * p],     ah[t], bh);
                    mma16816(acc[t][2 * p],     ah[t], bl);
                    mma16816(acc[t][2 * p],     al[t], bh);
                    mma16816(acc[t][2 * p + 1], ah[t], bh + 2);
                    mma16816(acc[t][2 * p + 1], ah[t], bl + 2);
                    mma16816(acc[t][2 * p + 1], al[t], bh + 2);
                }
            }
        }
        __syncthreads();
    }

    // stage O tile (+bias) to smem (aliases stage buffers; all MMAs complete)
#pragma unroll
    for (int t = 0; t < 2; t++) {
#pragma unroll
        for (int nt = 0; nt < NT; nt++) {
            int col = wn * WN + nt * 8 + (lane & 3) * 2;
            float b0 = bias[col0 + col], b1 = bias[col0 + col + 1];
#pragma unroll
            for (int h = 0; h < 2; h++) {
                int r = wm * 32 + t * 16 + (lane >> 2) + h * 8;
                sO[r * ROWF + col]     = acc[t][nt][2 * h + 0] + b0;
                sO[r * ROWF + col + 1] = acc[t][nt][2 * h + 1] + b1;
            }
        }
    }
    __syncthreads();

    // gate phase: 128 rows x 32 triples per CTA, 16 items/thread.
    // COALESCED mapping: j fast (32 consecutive threads -> 32 consecutive hidden
    // indices at one batch row).
#pragma unroll
    for (int it = 0; it < 16; it++) {
        int idx = tid + it * 256;
        int j = idx & 31, r = idx >> 5;        // j in 0..31, r in 0..127
        int b = row0 + r;
        int jg = blockIdx.x * 32 + j;          // global hidden index
        float o_r  = sO[r * ROWF + 3 * j];
        float o_z  = sO[r * ROWF + 3 * j + 1];
        float o_hn = sO[r * ROWF + 3 * j + 2];
        float innv = inn_s[(size_t)b * HH + jg];
        size_t hxi = (size_t)b * KCAT + jg;
        float hp = __bfloat162float(Ahi[hxi]) + __bfloat162float(Alo[hxi]);
        float rg = 1.f / (1.f + expf(-o_r));
        float zg = 1.f / (1.f + expf(-o_z));
        float n  = tanhf(innv + rg * o_hn);
        float hv = (1.f - zg) * n + zg * hp;
        bf16 hh, hl; fsplit(hv, hh, hl);
        hall_h[(size_t)b * HH + jg] = hh;      // lo plane dead (pred head is 2-term)
        hxw_h[hxi] = hh;
        hxw_l[hxi] = hl;
        // stage next x into the WRITE buffer (one writer per (b,a): jg<64)
        if (jg < AA && s < NSTEP - 1) {
            float xv = target[(size_t)b * (LL * AA) + (size_t)(s + 1) * AA + jg];
            bf16 xh, xl; fsplit(xv, xh, xl);
            hxw_h[(size_t)b * KCAT + HH + jg] = xh;
            hxw_l[(size_t)b * KCAT + HH + jg] = xl;
        }
    }
}

// -------------------- prep: interleaved wcat' + bias' + W_ihn planes --------------------
__global__ void prep_kernel(const float* __restrict__ W_hh, const float* __restrict__ W_ih,
                            const float* __restrict__ b_hh, const float* __restrict__ b_ih)
{
    int i = blockIdx.x * blockDim.x + threadIdx.x;
    if (i < NCAT * KCAT) {
        int n = i / KCAT, k = i % KCAT;
        int g = n % 3, jj = n / 3;             // interleaved row 3j+g
        int src = g * HH + jj;
        float v;
        if (k < HH)     v = W_hh[(size_t)src * HH + k];
        else if (g < 2) v = W_ih[(size_t)src * AA + (k - HH)];
        else            v = 0.f;               // n-gate x-part handled via precomputed inn
        fsplit(v, g_wc_h[i], g_wc_l[i]);
    }
    if (i < NCAT) {
        int g = i % 3, jj = i / 3;
        int src = g * HH + jj;
        g_bcat[i] = b_hh[src] + ((g < 2) ? b_ih[src] : 0.f);
    }
    if (i < HH * AA) {
        fsplit(W_ih[(size_t)(2 * HH) * AA + i], g_win_h[i], g_win_l[i]);
    }
}

// -------------------- split / xall / bos --------------------
__global__ void split_kernel(const float* __restrict__ src, bf16* __restrict__ hi,
                             bf16* __restrict__ lo, int n)
{
    int i = blockIdx.x * blockDim.x + threadIdx.x;
    if (i < n) fsplit(src[i], hi[i], lo[i]);
}

__global__ void xall_kernel(const float* __restrict__ target)
{
    int idx = blockIdx.x * blockDim.x + threadIdx.x;     // MALL*AA items
    if (idx >= MALL * AA) return;
    int m = idx >> 6, a = idx & 63;
    int s = m >> 12, b = m & (BB - 1);
    float v = (s == 0) ? ((a == 0) ? 16.f : -16.f)
                       : target[(size_t)b * (LL * AA) + (size_t)s * AA + a];
    fsplit(v, g_x_h[idx], g_x_l[idx]);
}

__global__ void bos_kernel(float* __restrict__ out)
{
    int i = blockIdx.x * blockDim.x + threadIdx.x;
    if (i >= BB * AA) return;
    int b = i >> 6, a = i & 63;
    float v = (a == 0) ? 16.f : -16.f;
    out[(size_t)b * (LL * AA) + a] = v;
    g_hx_h[(size_t)b * KCAT + HH + a] = __float2bfloat16(v);   // buffer 0 x-part (exact)
    g_hx_l[(size_t)b * KCAT + HH + a] = __float2bfloat16(0.f);
}

// -------------------- launch --------------------
extern "C" void kernel_launch(void* const* d_in, const int* in_sizes, int n_in,
                              void* d_out, int out_size)
{
    const float* latent = (const float*)d_in[0];
    const float* target = (const float*)d_in[1];
    const float* Wd1 = (const float*)d_in[2];
    const float* bd1 = (const float*)d_in[3];
    const float* Wd2 = (const float*)d_in[4];
    const float* bd2 = (const float*)d_in[5];
    const float* Wd3 = (const float*)d_in[6];
    const float* bd3 = (const float*)d_in[7];
    const float* W_ih = (const float*)d_in[8];
    const float* W_hh = (const float*)d_in[9];
    const float* b_ih = (const float*)d_in[10];
    const float* b_hh = (const float*)d_in[11];
    const float* Wm1 = (const float*)d_in[12];
    const float* bm1 = (const float*)d_in[13];
    const float* Wm2 = (const float*)d_in[14];
    const float* bm2 = (const float*)d_in[15];
    const float* Wm3 = (const float*)d_in[16];
    const float* bm3 = (const float*)d_in[17];
    float* out = (float*)d_out;

    bf16 *lath, *latl, *hxh, *hxl, *t1h, *t1l, *t2h, *t2l;
    bf16 *hallh, *p1h, *p2h, *xh, *xl;
    bf16 *wch, *wcl, *winh, *winl, *wd1h, *wd1l, *wd2h, *wd2l, *wd3h, *wd3l;
    bf16 *wm1h, *wm1l, *wm2h, *wm2l, *wm3h, *wm3l;
    float *inn, *bcat;
    cudaGetSymbolAddress((void**)&lath, g_lat_h);  cudaGetSymbolAddress((void**)&latl, g_lat_l);
    cudaGetSymbolAddress((void**)&hxh,  g_hx_h);   cudaGetSymbolAddress((void**)&hxl,  g_hx_l);
    cudaGetSymbolAddress((void**)&t1h,  g_t1_h);   cudaGetSymbolAddress((void**)&t1l,  g_t1_l);
    cudaGetSymbolAddress((void**)&t2h,  g_t2_h);   cudaGetSymbolAddress((void**)&t2l,  g_t2_l);
    cudaGetSymbolAddress((void**)&hallh,g_hall_h);
    cudaGetSymbolAddress((void**)&p1h,  g_p1_h);
    cudaGetSymbolAddress((void**)&p2h,  g_p2_h);
    cudaGetSymbolAddress((void**)&xh,   g_x_h);    cudaGetSymbolAddress((void**)&xl,   g_x_l);
    cudaGetSymbolAddress((void**)&wch,  g_wc_h);   cudaGetSymbolAddress((void**)&wcl,  g_wc_l);
    cudaGetSymbolAddress((void**)&winh, g_win_h);  cudaGetSymbolAddress((void**)&winl, g_win_l);
    cudaGetSymbolAddress((void**)&wd1h, g_wd1_h);  cudaGetSymbolAddress((void**)&wd1l, g_wd1_l);
    cudaGetSymbolAddress((void**)&wd2h, g_wd2_h);  cudaGetSymbolAddress((void**)&wd2l, g_wd2_l);
    cudaGetSymbolAddress((void**)&wd3h, g_wd3_h);  cudaGetSymbolAddress((void**)&wd3l, g_wd3_l);
    cudaGetSymbolAddress((void**)&wm1h, g_wm1_h);  cudaGetSymbolAddress((void**)&wm1l, g_wm1_l);
    cudaGetSymbolAddress((void**)&wm2h, g_wm2_h);  cudaGetSymbolAddress((void**)&wm2l, g_wm2_l);
    cudaGetSymbolAddress((void**)&wm3h, g_wm3_h);  cudaGetSymbolAddress((void**)&wm3l, g_wm3_l);
    cudaGetSymbolAddress((void**)&inn,  g_inn);
    cudaGetSymbolAddress((void**)&bcat, g_bcat);

    const int SM128_3 = 2 * (2 * 128 * 64 + 2 * 128 * 64);   // 65536
    const int SM128_2 = 2 * (1 * 128 * 64 + 2 * 128 * 64);   // 49152
    const int SM64_2  = 2 * (1 * 128 * 64 + 2 *  64 * 64);   // 32768
    cudaFuncSetAttribute(mma_gemm<128,3>, cudaFuncAttributeMaxDynamicSharedMemorySize, SM128_3);
    cudaFuncSetAttribute(mma_gemm<128,2>, cudaFuncAttributeMaxDynamicSharedMemorySize, SM128_2);
    cudaFuncSetAttribute(mma_gemm<64,2>,  cudaFuncAttributeMaxDynamicSharedMemorySize, SM64_2);
    cudaFuncSetAttribute(step_kernel,     cudaFuncAttributeMaxDynamicSharedMemorySize, ST_SMEM);

    // weight prep + input staging
    prep_kernel<<<(NCAT * KCAT + 255) / 256, 256>>>(W_hh, W_ih, b_hh, b_ih);
    split_kernel<<<(HH * LAT + 255) / 256, 256>>>(Wd1, wd1h, wd1l, HH * LAT);
    split_kernel<<<(HH * HH + 255) / 256, 256>>>(Wd2, wd2h, wd2l, HH * HH);
    split_kernel<<<(HH * HH + 255) / 256, 256>>>(Wd3, wd3h, wd3l, HH * HH);
    split_kernel<<<(HH * HH + 255) / 256, 256>>>(Wm1, wm1h, wm1l, HH * HH);
    split_kernel<<<(AA * HH + 255) / 256, 256>>>(Wm2, wm2h, wm2l, AA * HH);
    split_kernel<<<(AA * AA + 255) / 256, 256>>>(Wm3, wm3h, wm3l, AA * AA);
    split_kernel<<<(BB * LAT + 255) / 256, 256>>>(latent, lath, latl, BB * LAT);
    xall_kernel<<<(MALL * AA + 255) / 256, 256>>>(target);
    bos_kernel<<<(BB * AA + 255) / 256, 256>>>(out);

    // precompute inn[s,b,j] = x_s . W_ihn + b_ihn for ALL steps (one GEMM, 3-term:
    // feeds the recurrence, keep full precision)
    mma_gemm<128,3><<<dim3(HH / 128, MALL / 128), 256, SM128_3>>>(
        xh, xl, winh, winl, b_ih + 2 * HH, inn, nullptr, nullptr,
        MALL, HH, AA, HH, 0, 0);

    // initial hidden -> hx buffer 0 (3-term: feeds the recurrence)
    mma_gemm<128,3><<<dim3(HH / 128, BB / 128), 256, SM128_3>>>(
        lath, latl, wd1h, wd1l, bd1, nullptr, t1h, t1l, BB, HH, LAT, HH, 1, 1);
    mma_gemm<128,3><<<dim3(HH / 128, BB / 128), 256, SM128_3>>>(
        t1h, t1l, wd2h, wd2l, bd2, nullptr, t2h, t2l, BB, HH, HH, HH, 1, 1);
    mma_gemm<128,3><<<dim3(HH / 128, BB / 128), 256, SM128_3>>>(
        t2h, t2l, wd3h, wd3l, bd3, nullptr, hxh, hxl, BB, HH, HH, KCAT, 0, 1);

    // sequential GRU core: fused GEMM+gates (BK=64), ping-pong hx buffers
    for (int s = 0; s < NSTEP; s++) {
        const size_t rb = (size_t)(s & 1) * BB * KCAT;
        const size_t wb = (size_t)((s + 1) & 1) * BB * KCAT;
        step_kernel<<<dim3(NCAT / 96, BB / 128), 256, ST_SMEM>>>(
            hxh + rb, hxl + rb, wch, wcl, bcat,
            inn + (size_t)s * BB * HH, target,
            hxh + wb, hxl + wb,
            hallh + (size_t)s * BB * HH, s);
    }

    // deferred prediction head — output-facing, 2-term split; producers store
    // hi plane only (omode 3): the lo planes were write-only in R13.
    mma_gemm<128,2><<<dim3(HH / 128, MALL / 128), 256, SM128_2>>>(
        hallh, nullptr, wm1h, wm1l, bm1, nullptr, p1h, nullptr, MALL, HH, HH, HH, 1, 3);
    mma_gemm<64,2><<<dim3(1, MALL / 128), 256, SM64_2>>>(
        p1h, nullptr, wm2h, wm2l, bm2, nullptr, p2h, nullptr, MALL, AA, HH, AA, 1, 3);
    mma_gemm<64,2><<<dim3(1, MALL / 128), 256, SM64_2>>>(
        p2h, nullptr, wm3h, wm3l, bm3, out, nullptr, nullptr, MALL, AA, AA, 0, 0, 2);
}

// round 15
// speedup vs baseline: 2.6848x; 1.1908x over previous
#include <cuda_runtime.h>
#include <cuda_fp16.h>
#include <cstddef>
#include <cstdint>

// Problem constants
#define BB    4096      // batch
#define LAT   256
#define HH    512
#define AA    64
#define LL    128
#define NSTEP 127       // L-1 sequential GRU steps
#define KCAT  576       // H + A
#define NCAT  1536      // 3H
#define MALL  (NSTEP * BB)   // 520192 rows

typedef __half f16;

// -------------------- scratch (__device__ globals, no allocs) --------------------
__device__ __align__(256) f16   g_lat_h[BB * LAT],  g_lat_l[BB * LAT];
// ping-pong [h | x] buffers (read s&1, write (s+1)&1); h carried as fp16 hi+lo (~22 bits)
__device__ __align__(256) f16   g_hx_h [2 * BB * KCAT], g_hx_l [2 * BB * KCAT];
__device__ __align__(256) f16   g_t1_h [BB * HH],   g_t1_l [BB * HH];
__device__ __align__(256) f16   g_t2_h [BB * HH],   g_t2_l [BB * HH];
__device__ __align__(256) f16   g_hall [(size_t)MALL * HH];    // single plane: pred A input
__device__ __align__(256) f16   g_p1   [(size_t)MALL * HH];
__device__ __align__(256) f16   g_p2   [(size_t)MALL * AA];
// precomputed n-gate input projection for all steps: inn[s*BB+b][j]
__device__ __align__(256) float g_inn  [(size_t)MALL * HH];
// all-step inputs x as split planes [MALL x 64]
__device__ __align__(256) f16   g_x_h  [(size_t)MALL * AA], g_x_l[(size_t)MALL * AA];
// interleaved recurrent weight (single fp16 plane): row 3j+g <- [W_hh | W_ih(r,z) / 0(n)]
__device__ __align__(256) f16   g_wc   [NCAT * KCAT];
__device__ __align__(256) f16   g_win  [HH * AA];              // W_ih n-gate rows (single)
__device__ __align__(256) f16   g_wd1  [HH * LAT];             // prologue weights (single)
__device__ __align__(256) f16   g_wd2  [HH * HH];
__device__ __align__(256) f16   g_wd3  [HH * HH];
__device__ __align__(256) f16   g_wm1_h[HH * HH], g_wm1_l[HH * HH];   // pred weights (split)
__device__ __align__(256) f16   g_wm2_h[AA * HH], g_wm2_l[AA * HH];
__device__ __align__(256) f16   g_wm3_h[AA * AA], g_wm3_l[AA * AA];
__device__ __align__(256) float g_bcat[NCAT];          // interleaved triple bias

// -------------------- PTX helpers --------------------
__device__ __forceinline__ uint32_t smem_u32(const void* p) {
    return (uint32_t)__cvta_generic_to_shared(p);
}
__device__ __forceinline__ void cpasync16(uint32_t s, const void* g) {
    asm volatile("cp.async.cg.shared.global [%0], [%1], 16;\n" :: "r"(s), "l"(g));
}
__device__ __forceinline__ void ldmx4(uint32_t& r0, uint32_t& r1, uint32_t& r2, uint32_t& r3,
                                      uint32_t addr) {
    asm volatile("ldmatrix.sync.aligned.m8n8.x4.shared.b16 {%0,%1,%2,%3}, [%4];\n"
                 : "=r"(r0), "=r"(r1), "=r"(r2), "=r"(r3) : "r"(addr));
}
__device__ __forceinline__ void mma16816(float* c, const uint32_t* a, const uint32_t* b) {
    asm volatile(
        "mma.sync.aligned.m16n8k16.row.col.f32.f16.f16.f32 "
        "{%0,%1,%2,%3}, {%4,%5,%6,%7}, {%8,%9}, {%0,%1,%2,%3};\n"
        : "+f"(c[0]), "+f"(c[1]), "+f"(c[2]), "+f"(c[3])
        : "r"(a[0]), "r"(a[1]), "r"(a[2]), "r"(a[3]), "r"(b[0]), "r"(b[1]));
}
__device__ __forceinline__ void fsplit(float v, f16& h, f16& l) {
    h = __float2half(v);
    l = __float2half(v - __half2float(h));
}
// 64B-row swizzle (mma_gemm, BK=32): chunk q = c ^ ((r>>1)&3)
__device__ __forceinline__ uint32_t swz(int r, int c) {
    return (uint32_t)(r * 64 + ((c ^ ((r >> 1) & 3)) << 4));
}
// 128B-row swizzle (step_kernel, BK=64): chunk q = c ^ (r&7)
__device__ __forceinline__ uint32_t swz128(int r, int c) {
    return (uint32_t)(r * 128 + ((c ^ (r & 7)) << 4));
}

// -------------------- fp16 2-MMA split GEMM (generic) --------------------
// C[m,n] = act( sum_k A[m,k]*Bw[n,k] + bias[n] ), fp32 accum.
// ASPLIT=1: A = A0+A1 (hi+lo fp16, EXACT to ~22 bits), B = B0 single fp16.
//           acc = A0*B0 + A1*B0.  Error: B rounding only (~2^-12, systematic).
// ASPLIT=0: A = A0 single fp16, B = B0+B1 (hi+lo).  acc = A0*B0 + A0*B1.
//           Error: A rounding only. Used for the pred head.
// BM=128, BK=32, BN template. M%128==0, K%32==0.
// act: 0 none, 1 tanh.
// omode: 0 fp32 C, 1 split fp16 planes, 2 fp32 scatter to out, 3 fp16 single plane.
template<int BN, int ASPLIT>
__global__ void __launch_bounds__(256)
mma_gemm(const f16* __restrict__ A0, const f16* __restrict__ A1,
         const f16* __restrict__ B0, const f16* __restrict__ B1,
         const float* __restrict__ bias,
         float* __restrict__ Cf, f16* __restrict__ Ch, f16* __restrict__ Cl,
         int M, int N, int K, int ldc, int act, int omode)
{
    constexpr int WN  = BN / 2;
    constexpr int NT  = WN / 8;
    constexpr int NT2 = NT / 2;
    constexpr int A_BYTES = 128 * 64;
    constexpr int B_BYTES = BN * 64;
    // layout: ASPLIT=1 -> [A0][A1][B0] ; ASPLIT=0 -> [A0][B0][B1]
    constexpr int BOFF  = (ASPLIT ? 2 : 1) * A_BYTES;
    constexpr int STAGE = BOFF + (ASPLIT ? 1 : 2) * B_BYTES;

    extern __shared__ char smem[];
    const uint32_t sbase = smem_u32(smem);
    const int tid = threadIdx.x;
    const int lane = tid & 31, wid = tid >> 5;
    const int wm = wid & 3, wn = wid >> 2;
    const int row0 = blockIdx.y * 128;
    const int col0 = blockIdx.x * BN;
    const int KT = K >> 5;

    float acc[2][NT][4];
#pragma unroll
    for (int t = 0; t < 2; t++)
#pragma unroll
        for (int n = 0; n < NT; n++)
#pragma unroll
            for (int i = 0; i < 4; i++) acc[t][n][i] = 0.f;

    auto load_stage = [&](int kt, int s) {
        const int k0 = kt << 5;
        const uint32_t so = sbase + s * STAGE;
#pragma unroll
        for (int i = 0; i < 2; i++) {
            int l = tid + i * 256;
            int r = l >> 2, c = l & 3;
            uint32_t sa = so + swz(r, c);
            size_t go = (size_t)(row0 + r) * K + k0 + c * 8;
            cpasync16(sa, A0 + go);
            if (ASPLIT) cpasync16(sa + A_BYTES, A1 + go);
        }
#pragma unroll
        for (int i = 0; i < (BN * 4 + 255) / 256; i++) {
            int l = tid + i * 256;
            if (l < BN * 4) {
                int r = l >> 2, c = l & 3;
                uint32_t sb = so + BOFF + swz(r, c);
                size_t go = (size_t)(col0 + r) * K + k0 + c * 8;
                cpasync16(sb, B0 + go);
                if (!ASPLIT) cpasync16(sb + B_BYTES, B1 + go);
            }
        }
        asm volatile("cp.async.commit_group;\n" ::: "memory");
    };

    load_stage(0, 0);
    for (int kt = 0; kt < KT; kt++) {
        if (kt + 1 < KT) {
            load_stage(kt + 1, (kt + 1) & 1);
            asm volatile("cp.async.wait_group 1;\n" ::: "memory");
        } else {
            asm volatile("cp.async.wait_group 0;\n" ::: "memory");
        }
        __syncthreads();

        const uint32_t so = sbase + (kt & 1) * STAGE;
#pragma unroll
        for (int ks = 0; ks < 2; ks++) {
            uint32_t a0[2][4], a1[2][4];
#pragma unroll
            for (int t = 0; t < 2; t++) {
                int r = wm * 32 + t * 16 + (lane & 7) + ((lane >> 3) & 1) * 8;
                int c = ks * 2 + (lane >> 4);
                uint32_t addr = so + swz(r, c);
                ldmx4(a0[t][0], a0[t][1], a0[t][2], a0[t][3], addr);
                if (ASPLIT)
                    ldmx4(a1[t][0], a1[t][1], a1[t][2], a1[t][3], addr + A_BYTES);
            }
#pragma unroll
            for (int p = 0; p < NT2; p++) {
                int r = wn * WN + p * 16 + (lane & 7) + (lane >> 4) * 8;
                int c = ks * 2 + ((lane >> 3) & 1);
                uint32_t addr = so + BOFF + swz(r, c);
                uint32_t b0[4], b1[4];
                ldmx4(b0[0], b0[1], b0[2], b0[3], addr);
                if (!ASPLIT)
                    ldmx4(b1[0], b1[1], b1[2], b1[3], addr + B_BYTES);
#pragma unroll
                for (int t = 0; t < 2; t++) {
                    mma16816(acc[t][2 * p],     a0[t], b0);
                    mma16816(acc[t][2 * p + 1], a0[t], b0 + 2);
                    if (ASPLIT) {
                        mma16816(acc[t][2 * p],     a1[t], b0);
                        mma16816(acc[t][2 * p + 1], a1[t], b0 + 2);
                    } else {
                        mma16816(acc[t][2 * p],     a0[t], b1);
                        mma16816(acc[t][2 * p + 1], a0[t], b1 + 2);
                    }
                }
            }
        }
        __syncthreads();
    }

#pragma unroll
    for (int t = 0; t < 2; t++) {
#pragma unroll
        for (int nt = 0; nt < NT; nt++) {
            int col = col0 + wn * WN + nt * 8 + (lane & 3) * 2;
            float b0 = bias[col], b1 = bias[col + 1];
#pragma unroll
            for (int h = 0; h < 2; h++) {
                int m = row0 + wm * 32 + t * 16 + (lane >> 2) + h * 8;
                float vx = acc[t][nt][2 * h + 0] + b0;
                float vy = acc[t][nt][2 * h + 1] + b1;
                if (act) { vx = tanhf(vx); vy = tanhf(vy); }
                if (omode == 0) {
                    size_t idx = (size_t)m * ldc + col;
                    Cf[idx] = vx; Cf[idx + 1] = vy;
                } else if (omode == 1) {
                    size_t idx = (size_t)m * ldc + col;
                    f16 hx, lx; fsplit(vx, hx, lx);
                    f16 hy, ly; fsplit(vy, hy, ly);
                    Ch[idx] = hx; Ch[idx + 1] = hy;
                    Cl[idx] = lx; Cl[idx + 1] = ly;
                } else if (omode == 3) {
                    size_t idx = (size_t)m * ldc + col;
                    __half2 th; th.x = __float2half(vx); th.y = __float2half(vy);
                    *(__half2*)(Ch + idx) = th;
                } else {
                    int b = m & (BB - 1), s = m >> 12;
                    size_t idx = (size_t)b * (LL * AA) + (size_t)(s + 1) * AA + col;
                    Cf[idx] = vx; Cf[idx + 1] = vy;
                }
            }
        }
    }
}

// -------------------- fused GRU step: GEMM (interleaved triples) + gates --------------------
// fp16 A-split-exact: A = hx hi+lo planes, B = wcat single fp16. 2 MMAs per k-tile.
// BK=64 with SW128 swizzle. BN=96 so each CTA owns complete (r,z,n) triples.
#define ST_A 16384                 // 128 rows x 128B (one A plane, BK=64)
#define ST_B 12288                 // 96 rows x 128B (single B plane)
#define ST_STAGE (2 * ST_A + ST_B)           // 45056
#define ST_SMEM  (2 * ST_STAGE)              // 90112 (sO 128*97*4=49664 aliases)
#define ROWF 97

__global__ void __launch_bounds__(256)
step_kernel(const f16* __restrict__ A0, const f16* __restrict__ A1,      // read hx planes
            const f16* __restrict__ Bw,                                   // wcat single plane
            const float* __restrict__ bias,                               // bcat'
            const float* __restrict__ inn_s,                              // + s*BB*HH
            const float* __restrict__ target,
            f16* __restrict__ hxw_h, f16* __restrict__ hxw_l,             // write hx planes
            f16* __restrict__ hall,                                       // + s*BB*HH
            int s)
{
    constexpr int NT = 6, NT2 = 3, WN = 48;
    extern __shared__ char smem[];
    float* sO = (float*)smem;
    const uint32_t sbase = smem_u32(smem);
    const int tid = threadIdx.x;
    const int lane = tid & 31, wid = tid >> 5;
    const int wm = wid & 3, wn = wid >> 2;
    const int row0 = blockIdx.y * 128;
    const int col0 = blockIdx.x * 96;
    const int KT = KCAT >> 6;   // 9

    float acc[2][NT][4];
#pragma unroll
    for (int t = 0; t < 2; t++)
#pragma unroll
        for (int n = 0; n < NT; n++)
#pragma unroll
            for (int i = 0; i < 4; i++) acc[t][n][i] = 0.f;

    auto load_stage = [&](int kt, int st) {
        const int k0 = kt << 6;
        const uint32_t so = sbase + st * ST_STAGE;
#pragma unroll
        for (int i = 0; i < 4; i++) {                  // A: 1024 chunks x 2 planes
            int l = tid + i * 256;
            int r = l >> 3, c = l & 7;
            uint32_t sa = so + swz128(r, c);
            size_t go = (size_t)(row0 + r) * KCAT + k0 + c * 8;
            cpasync16(sa,        A0 + go);
            cpasync16(sa + ST_A, A1 + go);
        }
#pragma unroll
        for (int i = 0; i < 3; i++) {                  // B: 768 chunks x 1 plane
            int l = tid + i * 256;
            int r = l >> 3, c = l & 7;
            uint32_t sb = so + 2 * ST_A + swz128(r, c);
            size_t go = (size_t)(col0 + r) * KCAT + k0 + c * 8;
            cpasync16(sb, Bw + go);
        }
        asm volatile("cp.async.commit_group;\n" ::: "memory");
    };

    load_stage(0, 0);
    for (int kt = 0; kt < KT; kt++) {
        if (kt + 1 < KT) {
            load_stage(kt + 1, (kt + 1) & 1);
            asm volatile("cp.async.wait_group 1;\n" ::: "memory");
        } else {
            asm volatile("cp.async.wait_group 0;\n" ::: "memory");
        }
        __syncthreads();

        const uint32_t so = sbase + (kt & 1) * ST_STAGE;
#pragma unroll
        for (int ks = 0; ks < 4; ks++) {
            uint32_t a0[2][4], a1[2][4];
#pragma unroll
            for (int t = 0; t < 2; t++) {
                int r = wm * 32 + t * 16 + (lane & 7) + ((lane >> 3) & 1) * 8;
                int c = ks * 2 + (lane >> 4);
                uint32_t addr = so + swz128(r, c);
                ldmx4(a0[t][0], a0[t][1], a0[t][2], a0[t][3], addr);
                ldmx4(a1[t][0], a1[t][1], a1[t][2], a1[t][3], addr + ST_A);
            }
#pragma unroll
            for (int p = 0; p < NT2; p++) {
                int r = wn * WN + p * 16 + (lane & 7) + (lane >> 4) * 8;
                int c = ks * 2 + ((lane >> 3) & 1);
                uint32_t addr = so + 2 * ST_A + swz128(r, c);
                uint32_t b0[4];
                ldmx4(b0[0], b0[1], b0[2], b0[3], addr);
#pragma unroll
                for (int t = 0; t < 2; t++) {
                    mma16816(acc[t][2 * p],     a0[t], b0);
                    mma16816(acc[t][2 * p + 1], a0[t], b0 + 2);
                }
#pragma unroll
                for (int t = 0; t < 2; t++) {
                    mma16816(acc[t][2 * p],     a1[t], b0);
                    mma16816(acc[t][2 * p + 1], a1[t], b0 + 2);
                }
            }
        }
        __syncthreads();
    }

    // stage O tile (+bias) to smem (aliases stage buffers; all MMAs complete)
#pragma unroll
    for (int t = 0; t < 2; t++) {
#pragma unroll
        for (int nt = 0; nt < NT; nt++) {
            int col = wn * WN + nt * 8 + (lane & 3) * 2;
            float b0 = bias[col0 + col], b1 = bias[col0 + col + 1];
#pragma unroll
            for (int h = 0; h < 2; h++) {
                int r = wm * 32 + t * 16 + (lane >> 2) + h * 8;
                sO[r * ROWF + col]     = acc[t][nt][2 * h + 0] + b0;
                sO[r * ROWF + col + 1] = acc[t][nt][2 * h + 1] + b1;
            }
        }
    }
    __syncthreads();

    // gate phase: j-fast coalesced mapping (128 rows x 32 triples, 16 items/thread)
#pragma unroll
    for (int it = 0; it < 16; it++) {
        int idx = tid + it * 256;
        int j = idx & 31, r = idx >> 5;
        int b = row0 + r;
        int jg = blockIdx.x * 32 + j;
        float o_r  = sO[r * ROWF + 3 * j];
        float o_z  = sO[r * ROWF + 3 * j + 1];
        float o_hn = sO[r * ROWF + 3 * j + 2];
        float innv = inn_s[(size_t)b * HH + jg];
        size_t hxi = (size_t)b * KCAT + jg;
        float hp = __half2float(A0[hxi]) + __half2float(A1[hxi]);
        float rg = 1.f / (1.f + expf(-o_r));
        float zg = 1.f / (1.f + expf(-o_z));
        float n  = tanhf(innv + rg * o_hn);
        float hv = (1.f - zg) * n + zg * hp;
        f16 hh, hl; fsplit(hv, hh, hl);
        hall[(size_t)b * HH + jg] = hh;        // single plane (pred A is plain fp16)
        hxw_h[hxi] = hh;
        hxw_l[hxi] = hl;
        if (jg < AA && s < NSTEP - 1) {
            float xv = target[(size_t)b * (LL * AA) + (size_t)(s + 1) * AA + jg];
            f16 xh, xl; fsplit(xv, xh, xl);
            hxw_h[(size_t)b * KCAT + HH + jg] = xh;
            hxw_l[(size_t)b * KCAT + HH + jg] = xl;
        }
    }
}

// -------------------- prep: interleaved wcat (single fp16) + bias + win --------------------
__global__ void prep_kernel(const float* __restrict__ W_hh, const float* __restrict__ W_ih,
                            const float* __restrict__ b_hh, const float* __restrict__ b_ih)
{
    int i = blockIdx.x * blockDim.x + threadIdx.x;
    if (i < NCAT * KCAT) {
        int n = i / KCAT, k = i % KCAT;
        int g = n % 3, jj = n / 3;             // interleaved row 3j+g
        int src = g * HH + jj;
        float v;
        if (k < HH)     v = W_hh[(size_t)src * HH + k];
        else if (g < 2) v = W_ih[(size_t)src * AA + (k - HH)];
        else            v = 0.f;
        g_wc[i] = __float2half(v);
    }
    if (i < NCAT) {
        int g = i % 3, jj = i / 3;
        int src = g * HH + jj;
        g_bcat[i] = b_hh[src] + ((g < 2) ? b_ih[src] : 0.f);
    }
    if (i < HH * AA) {
        g_win[i] = __float2half(W_ih[(size_t)(2 * HH) * AA + i]);
    }
}

// -------------------- conv / split / xall / bos --------------------
__global__ void conv_kernel(const float* __restrict__ src, f16* __restrict__ dst, int n)
{
    int i = blockIdx.x * blockDim.x + threadIdx.x;
    if (i < n) dst[i] = __float2half(src[i]);
}

__global__ void split_kernel(const float* __restrict__ src, f16* __restrict__ hi,
                             f16* __restrict__ lo, int n)
{
    int i = blockIdx.x * blockDim.x + threadIdx.x;
    if (i < n) fsplit(src[i], hi[i], lo[i]);
}

__global__ void xall_kernel(const float* __restrict__ target)
{
    int idx = blockIdx.x * blockDim.x + threadIdx.x;
    if (idx >= MALL * AA) return;
    int m = idx >> 6, a = idx & 63;
    int s = m >> 12, b = m & (BB - 1);
    float v = (s == 0) ? ((a == 0) ? 16.f : -16.f)
                       : target[(size_t)b * (LL * AA) + (size_t)s * AA + a];
    fsplit(v, g_x_h[idx], g_x_l[idx]);
}

__global__ void bos_kernel(float* __restrict__ out)
{
    int i = blockIdx.x * blockDim.x + threadIdx.x;
    if (i >= BB * AA) return;
    int b = i >> 6, a = i & 63;
    float v = (a == 0) ? 16.f : -16.f;
    out[(size_t)b * (LL * AA) + a] = v;
    g_hx_h[(size_t)b * KCAT + HH + a] = __float2half(v);   // exact in fp16
    g_hx_l[(size_t)b * KCAT + HH + a] = __float2half(0.f);
}

// -------------------- launch --------------------
extern "C" void kernel_launch(void* const* d_in, const int* in_sizes, int n_in,
                              void* d_out, int out_size)
{
    const float* latent = (const float*)d_in[0];
    const float* target = (const float*)d_in[1];
    const float* Wd1 = (const float*)d_in[2];
    const float* bd1 = (const float*)d_in[3];
    const float* Wd2 = (const float*)d_in[4];
    const float* bd2 = (const float*)d_in[5];
    const float* Wd3 = (const float*)d_in[6];
    const float* bd3 = (const float*)d_in[7];
    const float* W_ih = (const float*)d_in[8];
    const float* W_hh = (const float*)d_in[9];
    const float* b_ih = (const float*)d_in[10];
    const float* b_hh = (const float*)d_in[11];
    const float* Wm1 = (const float*)d_in[12];
    const float* bm1 = (const float*)d_in[13];
    const float* Wm2 = (const float*)d_in[14];
    const float* bm2 = (const float*)d_in[15];
    const float* Wm3 = (const float*)d_in[16];
    const float* bm3 = (const float*)d_in[17];
    float* out = (float*)d_out;

    f16 *lath, *latl, *hxh, *hxl, *t1h, *t1l, *t2h, *t2l;
    f16 *hall, *p1, *p2, *xh, *xl;
    f16 *wc, *win, *wd1, *wd2, *wd3;
    f16 *wm1h, *wm1l, *wm2h, *wm2l, *wm3h, *wm3l;
    float *inn, *bcat;
    cudaGetSymbolAddress((void**)&lath, g_lat_h);  cudaGetSymbolAddress((void**)&latl, g_lat_l);
    cudaGetSymbolAddress((void**)&hxh,  g_hx_h);   cudaGetSymbolAddress((void**)&hxl,  g_hx_l);
    cudaGetSymbolAddress((void**)&t1h,  g_t1_h);   cudaGetSymbolAddress((void**)&t1l,  g_t1_l);
    cudaGetSymbolAddress((void**)&t2h,  g_t2_h);   cudaGetSymbolAddress((void**)&t2l,  g_t2_l);
    cudaGetSymbolAddress((void**)&hall, g_hall);
    cudaGetSymbolAddress((void**)&p1,   g_p1);
    cudaGetSymbolAddress((void**)&p2,   g_p2);
    cudaGetSymbolAddress((void**)&xh,   g_x_h);    cudaGetSymbolAddress((void**)&xl,   g_x_l);
    cudaGetSymbolAddress((void**)&wc,   g_wc);
    cudaGetSymbolAddress((void**)&win,  g_win);
    cudaGetSymbolAddress((void**)&wd1,  g_wd1);
    cudaGetSymbolAddress((void**)&wd2,  g_wd2);
    cudaGetSymbolAddress((void**)&wd3,  g_wd3);
    cudaGetSymbolAddress((void**)&wm1h, g_wm1_h);  cudaGetSymbolAddress((void**)&wm1l, g_wm1_l);
    cudaGetSymbolAddress((void**)&wm2h, g_wm2_h);  cudaGetSymbolAddress((void**)&wm2l, g_wm2_l);
    cudaGetSymbolAddress((void**)&wm3h, g_wm3_h);  cudaGetSymbolAddress((void**)&wm3l, g_wm3_l);
    cudaGetSymbolAddress((void**)&inn,  g_inn);
    cudaGetSymbolAddress((void**)&bcat, g_bcat);

    // smem: ASPLIT=1 BN=128: 2*(2*8192+8192)=49152 ; ASPLIT=0 BN=128: 49152 ; BN=64: 32768
    const int SM_A1_128 = 49152;
    const int SM_A0_128 = 49152;
    const int SM_A0_64  = 32768;
    cudaFuncSetAttribute(mma_gemm<128,1>, cudaFuncAttributeMaxDynamicSharedMemorySize, SM_A1_128);
    cudaFuncSetAttribute(mma_gemm<128,0>, cudaFuncAttributeMaxDynamicSharedMemorySize, SM_A0_128);
    cudaFuncSetAttribute(mma_gemm<64,0>,  cudaFuncAttributeMaxDynamicSharedMemorySize, SM_A0_64);
    cudaFuncSetAttribute(step_kernel,     cudaFuncAttributeMaxDynamicSharedMemorySize, ST_SMEM);

    // weight prep + input staging
    prep_kernel<<<(NCAT * KCAT + 255) / 256, 256>>>(W_hh, W_ih, b_hh, b_ih);
    conv_kernel<<<(HH * LAT + 255) / 256, 256>>>(Wd1, wd1, HH * LAT);
    conv_kernel<<<(HH * HH + 255) / 256, 256>>>(Wd2, wd2, HH * HH);
    conv_kernel<<<(HH * HH + 255) / 256, 256>>>(Wd3, wd3, HH * HH);
    split_kernel<<<(HH * HH + 255) / 256, 256>>>(Wm1, wm1h, wm1l, HH * HH);
    split_kernel<<<(AA * HH + 255) / 256, 256>>>(Wm2, wm2h, wm2l, AA * HH);
    split_kernel<<<(AA * AA + 255) / 256, 256>>>(Wm3, wm3h, wm3l, AA * AA);
    split_kernel<<<(BB * LAT + 255) / 256, 256>>>(latent, lath, latl, BB * LAT);
    xall_kernel<<<(MALL * AA + 255) / 256, 256>>>(target);
    bos_kernel<<<(BB * AA + 255) / 256, 256>>>(out);

    // precompute inn[s,b,j] = x_s . W_ihn + b_ihn (A=x split exact, B=win plain)
    mma_gemm<128,1><<<dim3(HH / 128, MALL / 128), 256, SM_A1_128>>>(
        xh, xl, win, nullptr, b_ih + 2 * HH, inn, nullptr, nullptr,
        MALL, HH, AA, HH, 0, 0);

    // initial hidden -> hx buffer 0 (A split exact, B plain)
    mma_gemm<128,1><<<dim3(HH / 128, BB / 128), 256, SM_A1_128>>>(
        lath, latl, wd1, nullptr, bd1, nullptr, t1h, t1l, BB, HH, LAT, HH, 1, 1);
    mma_gemm<128,1><<<dim3(HH / 128, BB / 128), 256, SM_A1_128>>>(
        t1h, t1l, wd2, nullptr, bd2, nullptr, t2h, t2l, BB, HH, HH, HH, 1, 1);
    mma_gemm<128,1><<<dim3(HH / 128, BB / 128), 256, SM_A1_128>>>(
        t2h, t2l, wd3, nullptr, bd3, nullptr, hxh, hxl, BB, HH, HH, KCAT, 0, 1);

    // sequential GRU core: fused GEMM+gates (fp16 A-split-exact, 2 MMAs/k-tile)
    for (int s = 0; s < NSTEP; s++) {
        const size_t rb = (size_t)(s & 1) * BB * KCAT;
        const size_t wb = (size_t)((s + 1) & 1) * BB * KCAT;
        step_kernel<<<dim3(NCAT / 96, BB / 128), 256, ST_SMEM>>>(
            hxh + rb, hxl + rb, wc, bcat,
            inn + (size_t)s * BB * HH, target,
            hxh + wb, hxl + wb,
            hall + (size_t)s * BB * HH, s);
    }

    // deferred prediction head (A plain fp16, B split: error = A-rounding only)
    mma_gemm<128,0><<<dim3(HH / 128, MALL / 128), 256, SM_A0_128>>>(
        hall, nullptr, wm1h, wm1l, bm1, nullptr, p1, nullptr, MALL, HH, HH, HH, 1, 3);
    mma_gemm<64,0><<<dim3(1, MALL / 128), 256, SM_A0_64>>>(
        p1, nullptr, wm2h, wm2l, bm2, nullptr, p2, nullptr, MALL, AA, HH, AA, 1, 3);
    mma_gemm<64,0><<<dim3(1, MALL / 128), 256, SM_A0_64>>>(
        p2, nullptr, wm3h, wm3l, bm3, out, nullptr, nullptr, MALL, AA, AA, 0, 0, 2);
}